// round 14
// baseline (speedup 1.0000x reference)
#include <cuda_runtime.h>
#include <cuda_bf16.h>
#include <cuda_fp16.h>
#include <math.h>

#define NMAX 100000
#define EMAX 1600000
#define FDIM 128
#define CDIM 64
#define SCAN_CH 512
#define NBLK ((NMAX + SCAN_CH - 1) / SCAN_CH)   // 196

// ---------------- device scratch (referenced ONLY in device code) ----------------
__device__ float g_dinv[NMAX];
__device__ __half g_y1h[NMAX * FDIM];  // y1 = x@W1 (unscaled, fp16 messages)
__device__ __half g_y2h[NMAX * CDIM];  // y2 = h@W2 (unscaled, fp16 messages)
__device__ __nv_bfloat16 g_xhi[NMAX * FDIM], g_xlo[NMAX * FDIM];   // split of x
__device__ __nv_bfloat16 g_hhi[NMAX * FDIM], g_hlo[NMAX * FDIM];   // split of h (relu out)
__device__ __nv_bfloat16 g_w1hi[FDIM * FDIM], g_w1lo[FDIM * FDIM]; // W1^T [n][k]
__device__ __nv_bfloat16 g_w2hi[CDIM * FDIM], g_w2lo[CDIM * FDIM]; // W2^T [n][k]
__device__ int   g_csr[EMAX];
__device__ int   g_cnt[NMAX];
__device__ int   g_off[NMAX + 1];
__device__ int   g_cur[NMAX];
__device__ int   g_bsum[NBLK];
__device__ int   g_is64;

// ---------------- prep: dtype detect (block 0) + zero cnt ----------------
__global__ void k_prep(const unsigned int* __restrict__ w, int n) {
    int i = blockIdx.x * blockDim.x + threadIdx.x;
    if (i < n) g_cnt[i] = 0;
    if (blockIdx.x == 0) {
        __shared__ unsigned int s;
        if (threadIdx.x == 0) s = 0u;
        __syncthreads();
        if (threadIdx.x < 128) atomicOr(&s, w[2 * threadIdx.x + 1]);  // int64 -> odd words 0
        __syncthreads();
        if (threadIdx.x == 0) g_is64 = (s == 0u) ? 1 : 0;
    }
}

// ---------------- f32 -> bf16 hi/lo split helpers ----------------
__device__ __forceinline__ void split1(float f, __nv_bfloat16& hi, __nv_bfloat16& lo) {
    hi = __float2bfloat16_rn(f);
    lo = __float2bfloat16_rn(f - __bfloat162float(hi));
}

__global__ void k_split_x(const float* __restrict__ X, int n4) {
    int i = blockIdx.x * blockDim.x + threadIdx.x;
    if (i >= n4) return;
    float4 v = ((const float4*)X)[i];
    __nv_bfloat16 h0, h1, h2, h3, l0, l1, l2, l3;
    split1(v.x, h0, l0); split1(v.y, h1, l1); split1(v.z, h2, l2); split1(v.w, h3, l3);
    uint2 uh, ul;
    uh.x = ((unsigned)__bfloat16_as_ushort(h1) << 16) | __bfloat16_as_ushort(h0);
    uh.y = ((unsigned)__bfloat16_as_ushort(h3) << 16) | __bfloat16_as_ushort(h2);
    ul.x = ((unsigned)__bfloat16_as_ushort(l1) << 16) | __bfloat16_as_ushort(l0);
    ul.y = ((unsigned)__bfloat16_as_ushort(l3) << 16) | __bfloat16_as_ushort(l2);
    ((uint2*)g_xhi)[i] = uh;
    ((uint2*)g_xlo)[i] = ul;
}

__global__ void k_split_w_both(const float* __restrict__ W1, const float* __restrict__ W2) {
    int i = blockIdx.x * blockDim.x + threadIdx.x;
    if (i < 128 * 128) {
        int k = i / 128, nn = i % 128;
        __nv_bfloat16 hi, lo;
        split1(W1[i], hi, lo);
        g_w1hi[nn * 128 + k] = hi;
        g_w1lo[nn * 128 + k] = lo;
    } else if (i < 128 * 128 + 128 * 64) {
        int j = i - 128 * 128;
        int k = j / 64, nn = j % 64;
        __nv_bfloat16 hi, lo;
        split1(W2[j], hi, lo);
        g_w2hi[nn * 128 + k] = hi;
        g_w2lo[nn * 128 + k] = lo;
    }
}

// ---------------- degree count ----------------
__global__ void k_count(const void* __restrict__ ei, int E) {
    int e = blockIdx.x * blockDim.x + threadIdx.x;
    if (e >= E) return;
    int d = g_is64 ? (int)((const long long*)ei)[E + e] : ((const int*)ei)[E + e];
    atomicAdd(&g_cnt[d], 1);
}

// ---------------- exclusive scan of g_cnt -> g_off (+ fused dinv) ----------------
__global__ void k_scan1(int n) {
    __shared__ int sm[SCAN_CH];
    int t = threadIdx.x, b = blockIdx.x;
    int i = b * SCAN_CH + t;
    int v = (i < n) ? g_cnt[i] : 0;
    if (i < n) g_dinv[i] = rsqrtf((float)(v + 1));
    sm[t] = v;
    __syncthreads();
#pragma unroll
    for (int off = 1; off < SCAN_CH; off <<= 1) {
        int tv = (t >= off) ? sm[t - off] : 0;
        __syncthreads();
        sm[t] += tv;
        __syncthreads();
    }
    if (i < n) g_off[i] = sm[t] - v;
    if (t == SCAN_CH - 1) g_bsum[b] = sm[t];
}

__global__ void k_scan2(int nb) {
    __shared__ int sm[256];
    int t = threadIdx.x;
    int v = (t < nb) ? g_bsum[t] : 0;
    sm[t] = v;
    __syncthreads();
#pragma unroll
    for (int off = 1; off < 256; off <<= 1) {
        int tv = (t >= off) ? sm[t - off] : 0;
        __syncthreads();
        sm[t] += tv;
        __syncthreads();
    }
    if (t < nb) g_bsum[t] = sm[t] - v;
}

__global__ void k_scan3(int n, int E) {
    int i = blockIdx.x * blockDim.x + threadIdx.x;
    if (i < n) {
        int o = g_off[i] + g_bsum[i / SCAN_CH];
        g_off[i] = o;
        g_cur[i] = o;
    }
    if (i == 0) g_off[n] = E;
}

__global__ void k_fill_csr(const void* __restrict__ ei, int E) {
    int e = blockIdx.x * blockDim.x + threadIdx.x;
    if (e >= E) return;
    int s, d;
    if (g_is64) {
        const long long* p = (const long long*)ei;
        s = (int)p[e];  d = (int)p[E + e];
    } else {
        const int* p = (const int*)ei;
        s = p[e];  d = p[E + e];
    }
    int pos = atomicAdd(&g_cur[d], 1);
    g_csr[pos] = s;
}

// ---------------- bf16 split-precision tensor-core GEMM (ldmatrix + swizzle) ----------------
__device__ __forceinline__ void mma16816(float* c, const unsigned* a, const unsigned* b) {
    asm volatile(
        "mma.sync.aligned.m16n8k16.row.col.f32.bf16.bf16.f32 "
        "{%0,%1,%2,%3}, {%4,%5,%6,%7}, {%8,%9}, {%0,%1,%2,%3};"
        : "+f"(c[0]), "+f"(c[1]), "+f"(c[2]), "+f"(c[3])
        : "r"(a[0]), "r"(a[1]), "r"(a[2]), "r"(a[3]), "r"(b[0]), "r"(b[1]));
}

__device__ __forceinline__ void ldsm4(unsigned* d, unsigned addr) {
    asm volatile("ldmatrix.sync.aligned.m8n8.x4.shared.b16 {%0,%1,%2,%3}, [%4];"
                 : "=r"(d[0]), "=r"(d[1]), "=r"(d[2]), "=r"(d[3]) : "r"(addr));
}

template <int NC, int LAYER>
__global__ __launch_bounds__(256, 2)
void k_gemm_mma(int n) {
    const __nv_bfloat16* Xhi = (LAYER == 0) ? g_xhi : g_hhi;
    const __nv_bfloat16* Xlo = (LAYER == 0) ? g_xlo : g_hlo;
    const __nv_bfloat16* Whi = (LAYER == 0) ? g_w1hi : g_w2hi;
    const __nv_bfloat16* Wlo = (LAYER == 0) ? g_w1lo : g_w2lo;
    __half*              Yh  = (LAYER == 0) ? g_y1h : g_y2h;

    constexpr int WM = (NC == 128) ? 2 : 4;
    constexpr int WN = 8 / WM;
    constexpr int WTM = 128 / WM;
    constexpr int WTN = NC / WN;
    constexpr int MF = WTM / 16;      // 4 / 2
    constexpr int NF = WTN / 8;       // 4
    constexpr int APLANE = 128 * 64;  // bf16 elems per A plane (128 rows x 128B)
    constexpr int BPLANE = NC * 64;   // bf16 elems per B k-plane

    extern __shared__ __nv_bfloat16 smb[];
    __nv_bfloat16* Ahi = smb;                       // APLANE
    __nv_bfloat16* Alo = Ahi + APLANE;              // APLANE
    __nv_bfloat16* Bhi = Alo + APLANE;              // 2*BPLANE (k-plane 0, 1)
    __nv_bfloat16* Blo = Bhi + 2 * BPLANE;          // 2*BPLANE

    const int t  = threadIdx.x;
    const int r0 = blockIdx.x * 128;

    // stage B both k-planes once (uint4 = 8 bf16, swizzled)
    for (int i = t; i < NC * 16; i += 256) {
        int row = i >> 4, c = i & 15;
        int p = c >> 3, cc = c & 7;
        int dst = p * BPLANE + row * 64 + ((cc ^ (row & 7)) << 3);
        *(uint4*)(Bhi + dst) = *(const uint4*)(Whi + row * 128 + p * 64 + cc * 8);
        *(uint4*)(Blo + dst) = *(const uint4*)(Wlo + row * 128 + p * 64 + cc * 8);
    }

    const int wid    = t >> 5;
    const int lane   = t & 31;
    const int warp_m = wid / WN;
    const int warp_n = wid % WN;
    const int g  = lane >> 2;
    const int tg = lane & 3;
    const int q  = lane >> 3;
    const int rr = lane & 7;

    const int qmA = ((q & 1) << 3) + rr;
    const int qkA = q >> 1;
    const int qnB = ((q >> 1) << 3) + rr;
    const int qkB = q & 1;

    const unsigned aHiU = (unsigned)__cvta_generic_to_shared(Ahi);
    const unsigned aLoU = (unsigned)__cvta_generic_to_shared(Alo);
    const unsigned bHiU = (unsigned)__cvta_generic_to_shared(Bhi);
    const unsigned bLoU = (unsigned)__cvta_generic_to_shared(Blo);

    const int rwarp = warp_m * WTM;
    const int cwarp = warp_n * WTN;

    unsigned arow[MF];
#pragma unroll
    for (int i = 0; i < MF; i++) arow[i] = (unsigned)(rwarp + i * 16 + qmA) * 128u;
    unsigned brow[NF / 2];
#pragma unroll
    for (int jp = 0; jp < NF / 2; jp++) brow[jp] = (unsigned)(cwarp + jp * 16 + qnB) * 128u;

    float c[MF][NF][4];
#pragma unroll
    for (int i = 0; i < MF; i++)
#pragma unroll
        for (int j = 0; j < NF; j++)
#pragma unroll
            for (int qq = 0; qq < 4; qq++) c[i][j][qq] = 0.0f;

    const uint4 z4 = make_uint4(0u, 0u, 0u, 0u);

#pragma unroll
    for (int kc = 0; kc < 2; kc++) {
        __syncthreads();
        for (int i = t; i < 128 * 8; i += 256) {
            int row = i >> 3, cc = i & 7;
            int grow = r0 + row;
            int dst = row * 64 + ((cc ^ (row & 7)) << 3);
            if (grow < n) {
                *(uint4*)(Ahi + dst) = *(const uint4*)(Xhi + (size_t)grow * 128 + kc * 64 + cc * 8);
                *(uint4*)(Alo + dst) = *(const uint4*)(Xlo + (size_t)grow * 128 + kc * 64 + cc * 8);
            } else {
                *(uint4*)(Ahi + dst) = z4;
                *(uint4*)(Alo + dst) = z4;
            }
        }
        __syncthreads();

        const unsigned bHiP = bHiU + (unsigned)(kc * BPLANE) * 2u;
        const unsigned bLoP = bLoU + (unsigned)(kc * BPLANE) * 2u;

#pragma unroll
        for (int ks = 0; ks < 4; ks++) {
            const int ck = ks * 2;
            unsigned ah[MF][4], al[MF][4], bh[NF][2], bl[NF][2];
#pragma unroll
            for (int i = 0; i < MF; i++) {
                unsigned off = arow[i] + (unsigned)(((ck + qkA) ^ rr) << 4);
                ldsm4(ah[i], aHiU + off);
                ldsm4(al[i], aLoU + off);
            }
#pragma unroll
            for (int jp = 0; jp < NF / 2; jp++) {
                unsigned off = brow[jp] + (unsigned)(((ck + qkB) ^ rr) << 4);
                unsigned tmp[4];
                ldsm4(tmp, bHiP + off);
                bh[2*jp][0] = tmp[0]; bh[2*jp][1] = tmp[1];
                bh[2*jp+1][0] = tmp[2]; bh[2*jp+1][1] = tmp[3];
                ldsm4(tmp, bLoP + off);
                bl[2*jp][0] = tmp[0]; bl[2*jp][1] = tmp[1];
                bl[2*jp+1][0] = tmp[2]; bl[2*jp+1][1] = tmp[3];
            }
#pragma unroll
            for (int i = 0; i < MF; i++)
#pragma unroll
                for (int j = 0; j < NF; j++) {
                    mma16816(c[i][j], ah[i], bh[j]);   // hi*hi
                    mma16816(c[i][j], ah[i], bl[j]);   // hi*lo
                    mma16816(c[i][j], al[i], bh[j]);   // lo*hi
                }
        }
    }

    // epilogue: store fp16 messages
#pragma unroll
    for (int i = 0; i < MF; i++) {
        int row0 = r0 + rwarp + i * 16 + g;
        int row1 = row0 + 8;
#pragma unroll
        for (int j = 0; j < NF; j++) {
            int col = cwarp + j * 8 + 2 * tg;
            if (row0 < n)
                *(__half2*)(Yh + (size_t)row0 * NC + col) = __floats2half2_rn(c[i][j][0], c[i][j][1]);
            if (row1 < n)
                *(__half2*)(Yh + (size_t)row1 * NC + col) = __floats2half2_rn(c[i][j][2], c[i][j][3]);
        }
    }
}

// ---------------- layer-1 gather (fp16 messages): h = relu(dinv_n*(Σ dinv_s*y1[s] + dinv_n*y1[n]) + b) ----------------
__global__ __launch_bounds__(256)
void k_gather_relu(const float* __restrict__ b, int n) {
    int node = (blockIdx.x * blockDim.x + threadIdx.x) >> 5;
    int lane = threadIdx.x & 31;
    if (node >= n) return;

    int e0 = g_off[node], e1 = g_off[node + 1];
    float sn = g_dinv[node];

    // each lane owns 4 consecutive values: 8B fp16 load per row
    __half2 w[2];
    *(uint2*)w = *(const uint2*)(g_y1h + (size_t)node * 128 + lane * 4);
    float2 f0 = __half22float2(w[0]);
    float2 f1 = __half22float2(w[1]);
    float4 a0 = make_float4(f0.x * sn, f0.y * sn, f1.x * sn, f1.y * sn);
    float4 a1 = make_float4(0.f, 0.f, 0.f, 0.f);
    float4 a2 = make_float4(0.f, 0.f, 0.f, 0.f);
    float4 a3 = make_float4(0.f, 0.f, 0.f, 0.f);

    int e = e0;
    for (; e + 3 < e1; e += 4) {
        int s0 = g_csr[e], s1 = g_csr[e+1], s2 = g_csr[e+2], s3 = g_csr[e+3];
        float d0 = g_dinv[s0], d1 = g_dinv[s1], d2 = g_dinv[s2], d3 = g_dinv[s3];
        __half2 w0[2], w1[2], w2[2], w3[2];
        *(uint2*)w0 = *(const uint2*)(g_y1h + (size_t)s0 * 128 + lane * 4);
        *(uint2*)w1 = *(const uint2*)(g_y1h + (size_t)s1 * 128 + lane * 4);
        *(uint2*)w2 = *(const uint2*)(g_y1h + (size_t)s2 * 128 + lane * 4);
        *(uint2*)w3 = *(const uint2*)(g_y1h + (size_t)s3 * 128 + lane * 4);
        float2 p0 = __half22float2(w0[0]), q0 = __half22float2(w0[1]);
        float2 p1 = __half22float2(w1[0]), q1 = __half22float2(w1[1]);
        float2 p2 = __half22float2(w2[0]), q2 = __half22float2(w2[1]);
        float2 p3 = __half22float2(w3[0]), q3 = __half22float2(w3[1]);
        a0.x = fmaf(p0.x, d0, a0.x); a0.y = fmaf(p0.y, d0, a0.y); a0.z = fmaf(q0.x, d0, a0.z); a0.w = fmaf(q0.y, d0, a0.w);
        a1.x = fmaf(p1.x, d1, a1.x); a1.y = fmaf(p1.y, d1, a1.y); a1.z = fmaf(q1.x, d1, a1.z); a1.w = fmaf(q1.y, d1, a1.w);
        a2.x = fmaf(p2.x, d2, a2.x); a2.y = fmaf(p2.y, d2, a2.y); a2.z = fmaf(q2.x, d2, a2.z); a2.w = fmaf(q2.y, d2, a2.w);
        a3.x = fmaf(p3.x, d3, a3.x); a3.y = fmaf(p3.y, d3, a3.y); a3.z = fmaf(q3.x, d3, a3.z); a3.w = fmaf(q3.y, d3, a3.w);
    }
    for (; e < e1; e++) {
        int s0 = g_csr[e];
        float d0 = g_dinv[s0];
        __half2 w0[2];
        *(uint2*)w0 = *(const uint2*)(g_y1h + (size_t)s0 * 128 + lane * 4);
        float2 p0 = __half22float2(w0[0]), q0 = __half22float2(w0[1]);
        a0.x = fmaf(p0.x, d0, a0.x); a0.y = fmaf(p0.y, d0, a0.y); a0.z = fmaf(q0.x, d0, a0.z); a0.w = fmaf(q0.y, d0, a0.w);
    }

    const float2* b2p = (const float2*)b;
    float2 bb0 = b2p[lane * 2], bb1 = b2p[lane * 2 + 1];
    float o0 = fmaxf(fmaf(sn, (a0.x + a1.x) + (a2.x + a3.x), bb0.x), 0.0f);
    float o1 = fmaxf(fmaf(sn, (a0.y + a1.y) + (a2.y + a3.y), bb0.y), 0.0f);
    float o2 = fmaxf(fmaf(sn, (a0.z + a1.z) + (a2.z + a3.z), bb1.x), 0.0f);
    float o3 = fmaxf(fmaf(sn, (a0.w + a1.w) + (a2.w + a3.w), bb1.y), 0.0f);

    __nv_bfloat16 h0, h1, h2, h3, l0, l1, l2, l3;
    split1(o0, h0, l0); split1(o1, h1, l1); split1(o2, h2, l2); split1(o3, h3, l3);
    uint2 uh, ul;
    uh.x = ((unsigned)__bfloat16_as_ushort(h1) << 16) | __bfloat16_as_ushort(h0);
    uh.y = ((unsigned)__bfloat16_as_ushort(h3) << 16) | __bfloat16_as_ushort(h2);
    ul.x = ((unsigned)__bfloat16_as_ushort(l1) << 16) | __bfloat16_as_ushort(l0);
    ul.y = ((unsigned)__bfloat16_as_ushort(l3) << 16) | __bfloat16_as_ushort(l2);
    ((uint2*)g_hhi)[(size_t)node * 32 + lane] = uh;
    ((uint2*)g_hlo)[(size_t)node * 32 + lane] = ul;
}

// ---------------- layer-2 gather (fp16 messages) + bias + log_softmax ----------------
__global__ __launch_bounds__(256)
void k_gather_lsm(const float* __restrict__ b, float* __restrict__ out, int n) {
    int node = (blockIdx.x * blockDim.x + threadIdx.x) >> 5;
    int lane = threadIdx.x & 31;
    if (node >= n) return;

    int e0 = g_off[node], e1 = g_off[node + 1];
    float sn = g_dinv[node];

    float2 f = __half22float2(*(const __half2*)(g_y2h + (size_t)node * 64 + lane * 2));
    float2 a0 = make_float2(f.x * sn, f.y * sn);
    float2 a1 = make_float2(0.f, 0.f);
    float2 a2 = make_float2(0.f, 0.f);
    float2 a3 = make_float2(0.f, 0.f);

    int e = e0;
    for (; e + 3 < e1; e += 4) {
        int s0 = g_csr[e], s1 = g_csr[e+1], s2 = g_csr[e+2], s3 = g_csr[e+3];
        float d0 = g_dinv[s0], d1 = g_dinv[s1], d2 = g_dinv[s2], d3 = g_dinv[s3];
        float2 v0 = __half22float2(*(const __half2*)(g_y2h + (size_t)s0 * 64 + lane * 2));
        float2 v1 = __half22float2(*(const __half2*)(g_y2h + (size_t)s1 * 64 + lane * 2));
        float2 v2 = __half22float2(*(const __half2*)(g_y2h + (size_t)s2 * 64 + lane * 2));
        float2 v3 = __half22float2(*(const __half2*)(g_y2h + (size_t)s3 * 64 + lane * 2));
        a0.x = fmaf(v0.x, d0, a0.x); a0.y = fmaf(v0.y, d0, a0.y);
        a1.x = fmaf(v1.x, d1, a1.x); a1.y = fmaf(v1.y, d1, a1.y);
        a2.x = fmaf(v2.x, d2, a2.x); a2.y = fmaf(v2.y, d2, a2.y);
        a3.x = fmaf(v3.x, d3, a3.x); a3.y = fmaf(v3.y, d3, a3.y);
    }
    for (; e < e1; e++) {
        int s0 = g_csr[e];
        float d0 = g_dinv[s0];
        float2 v0 = __half22float2(*(const __half2*)(g_y2h + (size_t)s0 * 64 + lane * 2));
        a0.x = fmaf(v0.x, d0, a0.x); a0.y = fmaf(v0.y, d0, a0.y);
    }

    float2 bb = ((const float2*)b)[lane];
    float t0 = fmaf(sn, (a0.x + a1.x) + (a2.x + a3.x), bb.x);
    float t1 = fmaf(sn, (a0.y + a1.y) + (a2.y + a3.y), bb.y);

    float m = fmaxf(t0, t1);
#pragma unroll
    for (int o = 16; o; o >>= 1) m = fmaxf(m, __shfl_xor_sync(0xffffffffu, m, o));
    float ex = expf(t0 - m) + expf(t1 - m);
#pragma unroll
    for (int o = 16; o; o >>= 1) ex += __shfl_xor_sync(0xffffffffu, ex, o);
    float ls = m + logf(ex);

    ((float2*)out)[(size_t)node * 32 + lane] = make_float2(t0 - ls, t1 - ls);
}

// ---------------- host launch ----------------
extern "C" void kernel_launch(void* const* d_in, const int* in_sizes, int n_in,
                              void* d_out, int out_size) {
    const float* x   = (const float*)d_in[0];
    const void*  ei  = d_in[1];
    const float* W1  = (const float*)d_in[2];
    const float* b1  = (const float*)d_in[3];
    const float* W2  = (const float*)d_in[4];
    const float* b2  = (const float*)d_in[5];
    float*       out = (float*)d_out;

    const int N = in_sizes[0] / FDIM;      // 100000
    const int E = in_sizes[1] / 2;         // 1600000

    const int SMEM1 = (2 * 128 * 64 + 4 * 128 * 64) * (int)sizeof(__nv_bfloat16);  // 98304
    const int SMEM2 = (2 * 128 * 64 + 4 * 64  * 64) * (int)sizeof(__nv_bfloat16);  // 65536
    cudaFuncSetAttribute(k_gemm_mma<128, 0>, cudaFuncAttributeMaxDynamicSharedMemorySize, SMEM1);
    cudaFuncSetAttribute(k_gemm_mma<64, 1>,  cudaFuncAttributeMaxDynamicSharedMemorySize, SMEM2);

    static cudaStream_t s2 = nullptr;
    static cudaEvent_t  evFork = nullptr, evJoin = nullptr;
    if (!s2) {
        cudaStreamCreateWithFlags(&s2, cudaStreamNonBlocking);
        cudaEventCreateWithFlags(&evFork, cudaEventDisableTiming);
        cudaEventCreateWithFlags(&evJoin, cudaEventDisableTiming);
    }

    const int nb = (N + SCAN_CH - 1) / SCAN_CH;

    // main stream: prep, then GEMM chain
    k_prep        <<<(N + 255) / 256, 256>>>((const unsigned int*)ei, N);        // 0
    cudaEventRecord(evFork, 0);
    k_split_x     <<<(N * 32 + 255) / 256, 256>>>(x, N * 32);                    // 1
    k_split_w_both<<<(128 * 192 + 255) / 256, 256>>>(W1, W2);                    // 2
    k_gemm_mma<128, 0><<<(N + 127) / 128, 256, SMEM1>>>(N);                      // 3 <- profiled

    // side stream: CSR build chain
    cudaStreamWaitEvent(s2, evFork, 0);
    k_count   <<<(E + 255) / 256, 256, 0, s2>>>(ei, E);
    k_scan1   <<<nb, SCAN_CH, 0, s2>>>(N);
    k_scan2   <<<1, 256, 0, s2>>>(nb);
    k_scan3   <<<(N + 255) / 256, 256, 0, s2>>>(N, E);
    k_fill_csr<<<(E + 255) / 256, 256, 0, s2>>>(ei, E);
    cudaEventRecord(evJoin, s2);

    // join, then aggregation + layer 2
    cudaStreamWaitEvent(0, evJoin, 0);
    k_gather_relu<<<(N * 32 + 255) / 256, 256>>>(b1, N);
    k_gemm_mma<64, 1><<<(N + 127) / 128, 256, SMEM2>>>(N);
    k_gather_lsm<<<(N * 32 + 255) / 256, 256>>>(b2, out, N);
}

// round 15
// speedup vs baseline: 1.1178x; 1.1178x over previous
#include <cuda_runtime.h>
#include <cuda_bf16.h>
#include <math.h>

#define NMAX 100000
#define EMAX 1600000
#define FDIM 128
#define CDIM 64
#define SCAN_CH 512
#define NBLK ((NMAX + SCAN_CH - 1) / SCAN_CH)   // 196

// ---------------- device scratch (referenced ONLY in device code) ----------------
__device__ float g_dinv[NMAX];
__device__ float g_y1 [NMAX * FDIM];   // y1 = x@W1 (unscaled, f32 messages)
__device__ float g_y2 [NMAX * CDIM];   // y2 = h@W2 (unscaled, f32 messages)
__device__ __nv_bfloat16 g_hhi[NMAX * FDIM], g_hlo[NMAX * FDIM];   // split of h (relu out)
__device__ __nv_bfloat16 g_w1hi[FDIM * FDIM], g_w1lo[FDIM * FDIM]; // W1^T [n][k]
__device__ __nv_bfloat16 g_w2hi[CDIM * FDIM], g_w2lo[CDIM * FDIM]; // W2^T [n][k]
__device__ int   g_csr[EMAX];
__device__ int   g_cnt[NMAX];
__device__ int   g_off[NMAX + 1];
__device__ int   g_cur[NMAX];
__device__ int   g_bsum[NBLK];
__device__ int   g_is64;

// ---------------- prep: dtype detect (block 0) + zero cnt ----------------
__global__ void k_prep(const unsigned int* __restrict__ w, int n) {
    int i = blockIdx.x * blockDim.x + threadIdx.x;
    if (i < n) g_cnt[i] = 0;
    if (blockIdx.x == 0) {
        __shared__ unsigned int s;
        if (threadIdx.x == 0) s = 0u;
        __syncthreads();
        if (threadIdx.x < 128) atomicOr(&s, w[2 * threadIdx.x + 1]);  // int64 -> odd words 0
        __syncthreads();
        if (threadIdx.x == 0) g_is64 = (s == 0u) ? 1 : 0;
    }
}

// ---------------- f32 -> bf16 hi/lo split helpers ----------------
__device__ __forceinline__ void split1(float f, __nv_bfloat16& hi, __nv_bfloat16& lo) {
    hi = __float2bfloat16_rn(f);
    lo = __float2bfloat16_rn(f - __bfloat162float(hi));
}

// split W1 into transposed [n][k] bf16 hi/lo
__global__ void k_split_w1(const float* __restrict__ W1) {
    int i = blockIdx.x * blockDim.x + threadIdx.x;
    if (i >= 128 * 128) return;
    int k = i / 128, nn = i % 128;
    __nv_bfloat16 hi, lo;
    split1(W1[i], hi, lo);
    g_w1hi[nn * 128 + k] = hi;
    g_w1lo[nn * 128 + k] = lo;
}

// split W2 into transposed [n][k] bf16 hi/lo
__global__ void k_split_w2(const float* __restrict__ W2) {
    int i = blockIdx.x * blockDim.x + threadIdx.x;
    if (i >= 128 * 64) return;
    int k = i / 64, nn = i % 64;
    __nv_bfloat16 hi, lo;
    split1(W2[i], hi, lo);
    g_w2hi[nn * 128 + k] = hi;
    g_w2lo[nn * 128 + k] = lo;
}

// ---------------- degree count ----------------
__global__ void k_count(const void* __restrict__ ei, int E) {
    int e = blockIdx.x * blockDim.x + threadIdx.x;
    if (e >= E) return;
    int d = g_is64 ? (int)((const long long*)ei)[E + e] : ((const int*)ei)[E + e];
    atomicAdd(&g_cnt[d], 1);
}

// ---------------- exclusive scan of g_cnt -> g_off (+ fused dinv) ----------------
__global__ void k_scan1(int n) {
    __shared__ int sm[SCAN_CH];
    int t = threadIdx.x, b = blockIdx.x;
    int i = b * SCAN_CH + t;
    int v = (i < n) ? g_cnt[i] : 0;
    if (i < n) g_dinv[i] = rsqrtf((float)(v + 1));
    sm[t] = v;
    __syncthreads();
#pragma unroll
    for (int off = 1; off < SCAN_CH; off <<= 1) {
        int tv = (t >= off) ? sm[t - off] : 0;
        __syncthreads();
        sm[t] += tv;
        __syncthreads();
    }
    if (i < n) g_off[i] = sm[t] - v;
    if (t == SCAN_CH - 1) g_bsum[b] = sm[t];
}

__global__ void k_scan2(int nb) {
    __shared__ int sm[256];
    int t = threadIdx.x;
    int v = (t < nb) ? g_bsum[t] : 0;
    sm[t] = v;
    __syncthreads();
#pragma unroll
    for (int off = 1; off < 256; off <<= 1) {
        int tv = (t >= off) ? sm[t - off] : 0;
        __syncthreads();
        sm[t] += tv;
        __syncthreads();
    }
    if (t < nb) g_bsum[t] = sm[t] - v;
}

__global__ void k_scan3(int n, int E) {
    int i = blockIdx.x * blockDim.x + threadIdx.x;
    if (i < n) {
        int o = g_off[i] + g_bsum[i / SCAN_CH];
        g_off[i] = o;
        g_cur[i] = o;
    }
    if (i == 0) g_off[n] = E;
}

__global__ void k_fill_csr(const void* __restrict__ ei, int E) {
    int e = blockIdx.x * blockDim.x + threadIdx.x;
    if (e >= E) return;
    int s, d;
    if (g_is64) {
        const long long* p = (const long long*)ei;
        s = (int)p[e];  d = (int)p[E + e];
    } else {
        const int* p = (const int*)ei;
        s = p[e];  d = p[E + e];
    }
    int pos = atomicAdd(&g_cur[d], 1);
    g_csr[pos] = s;
}

// ---------------- bf16 split-precision tensor-core GEMM (ldmatrix + swizzle) ----------------
// LAYER 0: reads f32 x directly, splits to bf16 hi/lo during staging (once per row chip-wide).
// LAYER 1: reads pre-split g_hhi/g_hlo.
__device__ __forceinline__ void mma16816(float* c, const unsigned* a, const unsigned* b) {
    asm volatile(
        "mma.sync.aligned.m16n8k16.row.col.f32.bf16.bf16.f32 "
        "{%0,%1,%2,%3}, {%4,%5,%6,%7}, {%8,%9}, {%0,%1,%2,%3};"
        : "+f"(c[0]), "+f"(c[1]), "+f"(c[2]), "+f"(c[3])
        : "r"(a[0]), "r"(a[1]), "r"(a[2]), "r"(a[3]), "r"(b[0]), "r"(b[1]));
}

__device__ __forceinline__ void ldsm4(unsigned* d, unsigned addr) {
    asm volatile("ldmatrix.sync.aligned.m8n8.x4.shared.b16 {%0,%1,%2,%3}, [%4];"
                 : "=r"(d[0]), "=r"(d[1]), "=r"(d[2]), "=r"(d[3]) : "r"(addr));
}

template <int NC, int LAYER>
__global__ __launch_bounds__(256, 2)
void k_gemm_mma(const float* __restrict__ Xf, int n) {
    const __nv_bfloat16* Whi = (LAYER == 0) ? g_w1hi : g_w2hi;
    const __nv_bfloat16* Wlo = (LAYER == 0) ? g_w1lo : g_w2lo;
    float*               Y   = (LAYER == 0) ? g_y1 : g_y2;

    constexpr int WM = (NC == 128) ? 2 : 4;
    constexpr int WN = 8 / WM;
    constexpr int WTM = 128 / WM;
    constexpr int WTN = NC / WN;
    constexpr int MF = WTM / 16;      // 4 / 2
    constexpr int NF = WTN / 8;       // 4
    constexpr int APLANE = 128 * 64;  // bf16 elems per A plane (128 rows x 128B)
    constexpr int BPLANE = NC * 64;   // bf16 elems per B k-plane

    extern __shared__ __nv_bfloat16 smb[];
    __nv_bfloat16* Ahi = smb;                       // APLANE
    __nv_bfloat16* Alo = Ahi + APLANE;              // APLANE
    __nv_bfloat16* Bhi = Alo + APLANE;              // 2*BPLANE (k-plane 0, 1)
    __nv_bfloat16* Blo = Bhi + 2 * BPLANE;          // 2*BPLANE

    const int t  = threadIdx.x;
    const int r0 = blockIdx.x * 128;

    // stage B both k-planes once (uint4 = 8 bf16, swizzled)
    for (int i = t; i < NC * 16; i += 256) {
        int row = i >> 4, c = i & 15;
        int p = c >> 3, cc = c & 7;
        int dst = p * BPLANE + row * 64 + ((cc ^ (row & 7)) << 3);
        *(uint4*)(Bhi + dst) = *(const uint4*)(Whi + row * 128 + p * 64 + cc * 8);
        *(uint4*)(Blo + dst) = *(const uint4*)(Wlo + row * 128 + p * 64 + cc * 8);
    }

    const int wid    = t >> 5;
    const int lane   = t & 31;
    const int warp_m = wid / WN;
    const int warp_n = wid % WN;
    const int g  = lane >> 2;
    const int tg = lane & 3;
    const int q  = lane >> 3;
    const int rr = lane & 7;

    const int qmA = ((q & 1) << 3) + rr;
    const int qkA = q >> 1;
    const int qnB = ((q >> 1) << 3) + rr;
    const int qkB = q & 1;

    const unsigned aHiU = (unsigned)__cvta_generic_to_shared(Ahi);
    const unsigned aLoU = (unsigned)__cvta_generic_to_shared(Alo);
    const unsigned bHiU = (unsigned)__cvta_generic_to_shared(Bhi);
    const unsigned bLoU = (unsigned)__cvta_generic_to_shared(Blo);

    const int rwarp = warp_m * WTM;
    const int cwarp = warp_n * WTN;

    unsigned arow[MF];
#pragma unroll
    for (int i = 0; i < MF; i++) arow[i] = (unsigned)(rwarp + i * 16 + qmA) * 128u;
    unsigned brow[NF / 2];
#pragma unroll
    for (int jp = 0; jp < NF / 2; jp++) brow[jp] = (unsigned)(cwarp + jp * 16 + qnB) * 128u;

    float c[MF][NF][4];
#pragma unroll
    for (int i = 0; i < MF; i++)
#pragma unroll
        for (int j = 0; j < NF; j++)
#pragma unroll
            for (int qq = 0; qq < 4; qq++) c[i][j][qq] = 0.0f;

    const uint4 z4 = make_uint4(0u, 0u, 0u, 0u);

#pragma unroll
    for (int kc = 0; kc < 2; kc++) {
        __syncthreads();
        // stage A k-chunk (swizzled)
        for (int i = t; i < 128 * 8; i += 256) {
            int row = i >> 3, cc = i & 7;
            int grow = r0 + row;
            int dst = row * 64 + ((cc ^ (row & 7)) << 3);
            uint4 uh = z4, ul = z4;
            if (grow < n) {
                if (LAYER == 0) {
                    // fused f32 -> bf16 hi/lo split (once per row chip-wide)
                    const float4* xp = (const float4*)(Xf + (size_t)grow * 128 + kc * 64 + cc * 8);
                    float4 va = xp[0], vb = xp[1];
                    float f[8] = {va.x, va.y, va.z, va.w, vb.x, vb.y, vb.z, vb.w};
                    unsigned hh[4], ll[4];
#pragma unroll
                    for (int q2 = 0; q2 < 4; q2++) {
                        __nv_bfloat16 h0, l0, h1, l1;
                        split1(f[2*q2],     h0, l0);
                        split1(f[2*q2 + 1], h1, l1);
                        hh[q2] = ((unsigned)__bfloat16_as_ushort(h1) << 16) | __bfloat16_as_ushort(h0);
                        ll[q2] = ((unsigned)__bfloat16_as_ushort(l1) << 16) | __bfloat16_as_ushort(l0);
                    }
                    uh = make_uint4(hh[0], hh[1], hh[2], hh[3]);
                    ul = make_uint4(ll[0], ll[1], ll[2], ll[3]);
                } else {
                    uh = *(const uint4*)(g_hhi + (size_t)grow * 128 + kc * 64 + cc * 8);
                    ul = *(const uint4*)(g_hlo + (size_t)grow * 128 + kc * 64 + cc * 8);
                }
            }
            *(uint4*)(Ahi + dst) = uh;
            *(uint4*)(Alo + dst) = ul;
        }
        __syncthreads();

        const unsigned bHiP = bHiU + (unsigned)(kc * BPLANE) * 2u;
        const unsigned bLoP = bLoU + (unsigned)(kc * BPLANE) * 2u;

#pragma unroll
        for (int ks = 0; ks < 4; ks++) {
            const int ck = ks * 2;
            unsigned ah[MF][4], al[MF][4], bh[NF][2], bl[NF][2];
#pragma unroll
            for (int i = 0; i < MF; i++) {
                unsigned off = arow[i] + (unsigned)(((ck + qkA) ^ rr) << 4);
                ldsm4(ah[i], aHiU + off);
                ldsm4(al[i], aLoU + off);
            }
#pragma unroll
            for (int jp = 0; jp < NF / 2; jp++) {
                unsigned off = brow[jp] + (unsigned)(((ck + qkB) ^ rr) << 4);
                unsigned tmp[4];
                ldsm4(tmp, bHiP + off);
                bh[2*jp][0] = tmp[0]; bh[2*jp][1] = tmp[1];
                bh[2*jp+1][0] = tmp[2]; bh[2*jp+1][1] = tmp[3];
                ldsm4(tmp, bLoP + off);
                bl[2*jp][0] = tmp[0]; bl[2*jp][1] = tmp[1];
                bl[2*jp+1][0] = tmp[2]; bl[2*jp+1][1] = tmp[3];
            }
#pragma unroll
            for (int i = 0; i < MF; i++)
#pragma unroll
                for (int j = 0; j < NF; j++) {
                    mma16816(c[i][j], ah[i], bh[j]);   // hi*hi
                    mma16816(c[i][j], ah[i], bl[j]);   // hi*lo
                    mma16816(c[i][j], al[i], bh[j]);   // lo*hi
                }
        }
    }

    // epilogue: plain f32 stores (dinv applied at gather time)
#pragma unroll
    for (int i = 0; i < MF; i++) {
        int row0 = r0 + rwarp + i * 16 + g;
        int row1 = row0 + 8;
#pragma unroll
        for (int j = 0; j < NF; j++) {
            int col = cwarp + j * 8 + 2 * tg;
            if (row0 < n)
                *(float2*)(Y + (size_t)row0 * NC + col) = make_float2(c[i][j][0], c[i][j][1]);
            if (row1 < n)
                *(float2*)(Y + (size_t)row1 * NC + col) = make_float2(c[i][j][2], c[i][j][3]);
        }
    }
}

// ---------------- layer-1 gather: h = relu(dinv_n*(dinv_n*y1[n] + Σ dinv_s*y1[s]) + b) ----------------
__global__ __launch_bounds__(256)
void k_gather_relu(const float* __restrict__ b, int n) {
    int node = (blockIdx.x * blockDim.x + threadIdx.x) >> 5;
    int lane = threadIdx.x & 31;
    if (node >= n) return;

    int e0 = g_off[node], e1 = g_off[node + 1];
    const float4* Y = (const float4*)g_y1;
    float sn = g_dinv[node];

    float4 sv = Y[(size_t)node * 32 + lane];
    float4 a0 = make_float4(sv.x * sn, sv.y * sn, sv.z * sn, sv.w * sn);
    float4 a1 = make_float4(0.f, 0.f, 0.f, 0.f);
    float4 a2 = make_float4(0.f, 0.f, 0.f, 0.f);
    float4 a3 = make_float4(0.f, 0.f, 0.f, 0.f);

    int e = e0;
    for (; e + 3 < e1; e += 4) {
        int s0 = g_csr[e], s1 = g_csr[e+1], s2 = g_csr[e+2], s3 = g_csr[e+3];
        float d0 = g_dinv[s0], d1 = g_dinv[s1], d2 = g_dinv[s2], d3 = g_dinv[s3];
        float4 v0 = Y[(size_t)s0 * 32 + lane];
        float4 v1 = Y[(size_t)s1 * 32 + lane];
        float4 v2 = Y[(size_t)s2 * 32 + lane];
        float4 v3 = Y[(size_t)s3 * 32 + lane];
        a0.x = fmaf(v0.x, d0, a0.x); a0.y = fmaf(v0.y, d0, a0.y); a0.z = fmaf(v0.z, d0, a0.z); a0.w = fmaf(v0.w, d0, a0.w);
        a1.x = fmaf(v1.x, d1, a1.x); a1.y = fmaf(v1.y, d1, a1.y); a1.z = fmaf(v1.z, d1, a1.z); a1.w = fmaf(v1.w, d1, a1.w);
        a2.x = fmaf(v2.x, d2, a2.x); a2.y = fmaf(v2.y, d2, a2.y); a2.z = fmaf(v2.z, d2, a2.z); a2.w = fmaf(v2.w, d2, a2.w);
        a3.x = fmaf(v3.x, d3, a3.x); a3.y = fmaf(v3.y, d3, a3.y); a3.z = fmaf(v3.z, d3, a3.z); a3.w = fmaf(v3.w, d3, a3.w);
    }
    for (; e < e1; e++) {
        int s0 = g_csr[e];
        float d0 = g_dinv[s0];
        float4 v0 = Y[(size_t)s0 * 32 + lane];
        a0.x = fmaf(v0.x, d0, a0.x); a0.y = fmaf(v0.y, d0, a0.y); a0.z = fmaf(v0.z, d0, a0.z); a0.w = fmaf(v0.w, d0, a0.w);
    }

    float4 bb = ((const float4*)b)[lane];
    float o0 = fmaxf(fmaf(sn, (a0.x + a1.x) + (a2.x + a3.x), bb.x), 0.0f);
    float o1 = fmaxf(fmaf(sn, (a0.y + a1.y) + (a2.y + a3.y), bb.y), 0.0f);
    float o2 = fmaxf(fmaf(sn, (a0.z + a1.z) + (a2.z + a3.z), bb.z), 0.0f);
    float o3 = fmaxf(fmaf(sn, (a0.w + a1.w) + (a2.w + a3.w), bb.w), 0.0f);

    __nv_bfloat16 h0, h1, h2, h3, l0, l1, l2, l3;
    split1(o0, h0, l0); split1(o1, h1, l1); split1(o2, h2, l2); split1(o3, h3, l3);
    uint2 uh, ul;
    uh.x = ((unsigned)__bfloat16_as_ushort(h1) << 16) | __bfloat16_as_ushort(h0);
    uh.y = ((unsigned)__bfloat16_as_ushort(h3) << 16) | __bfloat16_as_ushort(h2);
    ul.x = ((unsigned)__bfloat16_as_ushort(l1) << 16) | __bfloat16_as_ushort(l0);
    ul.y = ((unsigned)__bfloat16_as_ushort(l3) << 16) | __bfloat16_as_ushort(l2);
    ((uint2*)g_hhi)[(size_t)node * 32 + lane] = uh;
    ((uint2*)g_hlo)[(size_t)node * 32 + lane] = ul;
}

// ---------------- layer-2 gather + bias + log_softmax ----------------
__global__ __launch_bounds__(256)
void k_gather_lsm(const float* __restrict__ b, float* __restrict__ out, int n) {
    int node = (blockIdx.x * blockDim.x + threadIdx.x) >> 5;
    int lane = threadIdx.x & 31;
    if (node >= n) return;

    int e0 = g_off[node], e1 = g_off[node + 1];
    const float2* Y = (const float2*)g_y2;
    float sn = g_dinv[node];

    float2 sv = Y[(size_t)node * 32 + lane];
    float2 a0 = make_float2(sv.x * sn, sv.y * sn);
    float2 a1 = make_float2(0.f, 0.f);
    float2 a2 = make_float2(0.f, 0.f);
    float2 a3 = make_float2(0.f, 0.f);

    int e = e0;
    for (; e + 3 < e1; e += 4) {
        int s0 = g_csr[e], s1 = g_csr[e+1], s2 = g_csr[e+2], s3 = g_csr[e+3];
        float d0 = g_dinv[s0], d1 = g_dinv[s1], d2 = g_dinv[s2], d3 = g_dinv[s3];
        float2 v0 = Y[(size_t)s0 * 32 + lane];
        float2 v1 = Y[(size_t)s1 * 32 + lane];
        float2 v2 = Y[(size_t)s2 * 32 + lane];
        float2 v3 = Y[(size_t)s3 * 32 + lane];
        a0.x = fmaf(v0.x, d0, a0.x); a0.y = fmaf(v0.y, d0, a0.y);
        a1.x = fmaf(v1.x, d1, a1.x); a1.y = fmaf(v1.y, d1, a1.y);
        a2.x = fmaf(v2.x, d2, a2.x); a2.y = fmaf(v2.y, d2, a2.y);
        a3.x = fmaf(v3.x, d3, a3.x); a3.y = fmaf(v3.y, d3, a3.y);
    }
    for (; e < e1; e++) {
        int s0 = g_csr[e];
        float d0 = g_dinv[s0];
        float2 v0 = Y[(size_t)s0 * 32 + lane];
        a0.x = fmaf(v0.x, d0, a0.x); a0.y = fmaf(v0.y, d0, a0.y);
    }

    float2 bb = ((const float2*)b)[lane];
    float t0 = fmaf(sn, (a0.x + a1.x) + (a2.x + a3.x), bb.x);
    float t1 = fmaf(sn, (a0.y + a1.y) + (a2.y + a3.y), bb.y);

    float m = fmaxf(t0, t1);
#pragma unroll
    for (int o = 16; o; o >>= 1) m = fmaxf(m, __shfl_xor_sync(0xffffffffu, m, o));
    float ex = expf(t0 - m) + expf(t1 - m);
#pragma unroll
    for (int o = 16; o; o >>= 1) ex += __shfl_xor_sync(0xffffffffu, ex, o);
    float ls = m + logf(ex);

    ((float2*)out)[(size_t)node * 32 + lane] = make_float2(t0 - ls, t1 - ls);
}

// ---------------- host launch ----------------
extern "C" void kernel_launch(void* const* d_in, const int* in_sizes, int n_in,
                              void* d_out, int out_size) {
    const float* x   = (const float*)d_in[0];
    const void*  ei  = d_in[1];
    const float* W1  = (const float*)d_in[2];
    const float* b1  = (const float*)d_in[3];
    const float* W2  = (const float*)d_in[4];
    const float* b2  = (const float*)d_in[5];
    float*       out = (float*)d_out;

    const int N = in_sizes[0] / FDIM;      // 100000
    const int E = in_sizes[1] / 2;         // 1600000

    const int SMEM1 = (2 * 128 * 64 + 4 * 128 * 64) * (int)sizeof(__nv_bfloat16);  // 98304
    const int SMEM2 = (2 * 128 * 64 + 4 * 64  * 64) * (int)sizeof(__nv_bfloat16);  // 65536
    cudaFuncSetAttribute(k_gemm_mma<128, 0>, cudaFuncAttributeMaxDynamicSharedMemorySize, SMEM1);
    cudaFuncSetAttribute(k_gemm_mma<64, 1>,  cudaFuncAttributeMaxDynamicSharedMemorySize, SMEM2);

    static cudaStream_t s2 = nullptr;
    static cudaEvent_t  evFork = nullptr, evJoin = nullptr;
    if (!s2) {
        cudaStreamCreateWithFlags(&s2, cudaStreamNonBlocking);
        cudaEventCreateWithFlags(&evFork, cudaEventDisableTiming);
        cudaEventCreateWithFlags(&evJoin, cudaEventDisableTiming);
    }

    const int nb = (N + SCAN_CH - 1) / SCAN_CH;

    // main stream: prep, W splits, then layer-1 GEMM (x split fused into staging)
    k_prep    <<<(N + 255) / 256, 256>>>((const unsigned int*)ei, N);            // 0
    cudaEventRecord(evFork, 0);
    k_split_w1<<<(128 * 128 + 255) / 256, 256>>>(W1);                            // 1
    k_split_w2<<<(128 * 64 + 255) / 256, 256>>>(W2);                             // 2
    k_gemm_mma<128, 0><<<(N + 127) / 128, 256, SMEM1>>>(x, N);                   // 3 <- profiled

    // side stream: CSR build chain
    cudaStreamWaitEvent(s2, evFork, 0);
    k_count   <<<(E + 255) / 256, 256, 0, s2>>>(ei, E);
    k_scan1   <<<nb, SCAN_CH, 0, s2>>>(N);
    k_scan2   <<<1, 256, 0, s2>>>(nb);
    k_scan3   <<<(N + 255) / 256, 256, 0, s2>>>(N, E);
    k_fill_csr<<<(E + 255) / 256, 256, 0, s2>>>(ei, E);
    cudaEventRecord(evJoin, s2);

    // join, then aggregation + layer 2
    cudaStreamWaitEvent(0, evJoin, 0);
    k_gather_relu<<<(N * 32 + 255) / 256, 256>>>(b1, N);
    k_gemm_mma<64, 1><<<(N + 127) / 128, 256, SMEM2>>>(nullptr, N);
    k_gather_lsm<<<(N * 32 + 255) / 256, 256>>>(b2, out, N);
}

// round 16
// speedup vs baseline: 1.2830x; 1.1478x over previous
#include <cuda_runtime.h>
#include <cuda_bf16.h>
#include <math.h>

#define NMAX 100000
#define EMAX 1600000
#define FDIM 128
#define CDIM 64
#define SCAN_CH 512
#define NBLK ((NMAX + SCAN_CH - 1) / SCAN_CH)   // 196

// ---------------- device scratch (referenced ONLY in device code) ----------------
__device__ float g_dinv[NMAX];
__device__ float g_y1 [NMAX * FDIM];   // y1 = x@W1 (unscaled, f32 messages)
__device__ float g_y2 [NMAX * CDIM];   // y2 = h@W2 (unscaled, f32 messages)
__device__ __nv_bfloat16 g_xhi[NMAX * FDIM], g_xlo[NMAX * FDIM];   // split of x
__device__ __nv_bfloat16 g_hhi[NMAX * FDIM], g_hlo[NMAX * FDIM];   // split of h (relu out)
__device__ __nv_bfloat16 g_w1hi[FDIM * FDIM], g_w1lo[FDIM * FDIM]; // W1^T [n][k]
__device__ __nv_bfloat16 g_w2hi[CDIM * FDIM], g_w2lo[CDIM * FDIM]; // W2^T [n][k]
__device__ int   g_csr[EMAX];
__device__ int   g_cnt[NMAX];
__device__ int   g_off[NMAX + 1];
__device__ int   g_cur[NMAX];
__device__ int   g_bsum[NBLK];
__device__ int   g_is64;

// ---------------- prep: dtype detect (block 0) + zero cnt ----------------
__global__ void k_prep(const unsigned int* __restrict__ w, int n) {
    int i = blockIdx.x * blockDim.x + threadIdx.x;
    if (i < n) g_cnt[i] = 0;
    if (blockIdx.x == 0) {
        __shared__ unsigned int s;
        if (threadIdx.x == 0) s = 0u;
        __syncthreads();
        if (threadIdx.x < 128) atomicOr(&s, w[2 * threadIdx.x + 1]);  // int64 -> odd words 0
        __syncthreads();
        if (threadIdx.x == 0) g_is64 = (s == 0u) ? 1 : 0;
    }
}

// ---------------- f32 -> bf16 hi/lo split helpers ----------------
__device__ __forceinline__ void split1(float f, __nv_bfloat16& hi, __nv_bfloat16& lo) {
    hi = __float2bfloat16_rn(f);
    lo = __float2bfloat16_rn(f - __bfloat162float(hi));
}

__global__ void k_split_x(const float* __restrict__ X, int n4) {
    int i = blockIdx.x * blockDim.x + threadIdx.x;
    if (i >= n4) return;
    float4 v = ((const float4*)X)[i];
    __nv_bfloat16 h0, h1, h2, h3, l0, l1, l2, l3;
    split1(v.x, h0, l0); split1(v.y, h1, l1); split1(v.z, h2, l2); split1(v.w, h3, l3);
    uint2 uh, ul;
    uh.x = ((unsigned)__bfloat16_as_ushort(h1) << 16) | __bfloat16_as_ushort(h0);
    uh.y = ((unsigned)__bfloat16_as_ushort(h3) << 16) | __bfloat16_as_ushort(h2);
    ul.x = ((unsigned)__bfloat16_as_ushort(l1) << 16) | __bfloat16_as_ushort(l0);
    ul.y = ((unsigned)__bfloat16_as_ushort(l3) << 16) | __bfloat16_as_ushort(l2);
    ((uint2*)g_xhi)[i] = uh;
    ((uint2*)g_xlo)[i] = ul;
}

__global__ void k_split_w_both(const float* __restrict__ W1, const float* __restrict__ W2) {
    int i = blockIdx.x * blockDim.x + threadIdx.x;
    if (i < 128 * 128) {
        int k = i / 128, nn = i % 128;
        __nv_bfloat16 hi, lo;
        split1(W1[i], hi, lo);
        g_w1hi[nn * 128 + k] = hi;
        g_w1lo[nn * 128 + k] = lo;
    } else if (i < 128 * 128 + 128 * 64) {
        int j = i - 128 * 128;
        int k = j / 64, nn = j % 64;
        __nv_bfloat16 hi, lo;
        split1(W2[j], hi, lo);
        g_w2hi[nn * 128 + k] = hi;
        g_w2lo[nn * 128 + k] = lo;
    }
}

// ---------------- degree count ----------------
__global__ void k_count(const void* __restrict__ ei, int E) {
    int e = blockIdx.x * blockDim.x + threadIdx.x;
    if (e >= E) return;
    int d = g_is64 ? (int)((const long long*)ei)[E + e] : ((const int*)ei)[E + e];
    atomicAdd(&g_cnt[d], 1);
}

// ---------------- exclusive scan of g_cnt -> g_off (+ fused dinv) ----------------
__global__ void k_scan1(int n) {
    __shared__ int sm[SCAN_CH];
    int t = threadIdx.x, b = blockIdx.x;
    int i = b * SCAN_CH + t;
    int v = (i < n) ? g_cnt[i] : 0;
    if (i < n) g_dinv[i] = rsqrtf((float)(v + 1));
    sm[t] = v;
    __syncthreads();
#pragma unroll
    for (int off = 1; off < SCAN_CH; off <<= 1) {
        int tv = (t >= off) ? sm[t - off] : 0;
        __syncthreads();
        sm[t] += tv;
        __syncthreads();
    }
    if (i < n) g_off[i] = sm[t] - v;
    if (t == SCAN_CH - 1) g_bsum[b] = sm[t];
}

__global__ void k_scan2(int nb) {
    __shared__ int sm[256];
    int t = threadIdx.x;
    int v = (t < nb) ? g_bsum[t] : 0;
    sm[t] = v;
    __syncthreads();
#pragma unroll
    for (int off = 1; off < 256; off <<= 1) {
        int tv = (t >= off) ? sm[t - off] : 0;
        __syncthreads();
        sm[t] += tv;
        __syncthreads();
    }
    if (t < nb) g_bsum[t] = sm[t] - v;
}

__global__ void k_scan3(int n, int E) {
    int i = blockIdx.x * blockDim.x + threadIdx.x;
    if (i < n) {
        int o = g_off[i] + g_bsum[i / SCAN_CH];
        g_off[i] = o;
        g_cur[i] = o;
    }
    if (i == 0) g_off[n] = E;
}

__global__ void k_fill_csr(const void* __restrict__ ei, int E) {
    int e = blockIdx.x * blockDim.x + threadIdx.x;
    if (e >= E) return;
    int s, d;
    if (g_is64) {
        const long long* p = (const long long*)ei;
        s = (int)p[e];  d = (int)p[E + e];
    } else {
        const int* p = (const int*)ei;
        s = p[e];  d = p[E + e];
    }
    int pos = atomicAdd(&g_cur[d], 1);
    g_csr[pos] = s;
}

// ---------------- bf16 split-precision tensor-core GEMM (ldmatrix + swizzle) ----------------
__device__ __forceinline__ void mma16816(float* c, const unsigned* a, const unsigned* b) {
    asm volatile(
        "mma.sync.aligned.m16n8k16.row.col.f32.bf16.bf16.f32 "
        "{%0,%1,%2,%3}, {%4,%5,%6,%7}, {%8,%9}, {%0,%1,%2,%3};"
        : "+f"(c[0]), "+f"(c[1]), "+f"(c[2]), "+f"(c[3])
        : "r"(a[0]), "r"(a[1]), "r"(a[2]), "r"(a[3]), "r"(b[0]), "r"(b[1]));
}

__device__ __forceinline__ void ldsm4(unsigned* d, unsigned addr) {
    asm volatile("ldmatrix.sync.aligned.m8n8.x4.shared.b16 {%0,%1,%2,%3}, [%4];"
                 : "=r"(d[0]), "=r"(d[1]), "=r"(d[2]), "=r"(d[3]) : "r"(addr));
}

template <int NC, int LAYER>
__global__ __launch_bounds__(256, 2)
void k_gemm_mma(int n) {
    const __nv_bfloat16* Xhi = (LAYER == 0) ? g_xhi : g_hhi;
    const __nv_bfloat16* Xlo = (LAYER == 0) ? g_xlo : g_hlo;
    const __nv_bfloat16* Whi = (LAYER == 0) ? g_w1hi : g_w2hi;
    const __nv_bfloat16* Wlo = (LAYER == 0) ? g_w1lo : g_w2lo;
    float*               Y   = (LAYER == 0) ? g_y1 : g_y2;

    constexpr int WM = (NC == 128) ? 2 : 4;
    constexpr int WN = 8 / WM;
    constexpr int WTM = 128 / WM;
    constexpr int WTN = NC / WN;
    constexpr int MF = WTM / 16;      // 4 / 2
    constexpr int NF = WTN / 8;       // 4
    constexpr int APLANE = 128 * 64;  // bf16 elems per A plane (128 rows x 128B)
    constexpr int BPLANE = NC * 64;   // bf16 elems per B k-plane

    extern __shared__ __nv_bfloat16 smb[];
    __nv_bfloat16* Ahi = smb;
    __nv_bfloat16* Alo = Ahi + APLANE;
    __nv_bfloat16* Bhi = Alo + APLANE;
    __nv_bfloat16* Blo = Bhi + 2 * BPLANE;

    const int t  = threadIdx.x;
    const int r0 = blockIdx.x * 128;

    for (int i = t; i < NC * 16; i += 256) {
        int row = i >> 4, c = i & 15;
        int p = c >> 3, cc = c & 7;
        int dst = p * BPLANE + row * 64 + ((cc ^ (row & 7)) << 3);
        *(uint4*)(Bhi + dst) = *(const uint4*)(Whi + row * 128 + p * 64 + cc * 8);
        *(uint4*)(Blo + dst) = *(const uint4*)(Wlo + row * 128 + p * 64 + cc * 8);
    }

    const int wid    = t >> 5;
    const int lane   = t & 31;
    const int warp_m = wid / WN;
    const int warp_n = wid % WN;
    const int g  = lane >> 2;
    const int tg = lane & 3;
    const int q  = lane >> 3;
    const int rr = lane & 7;

    const int qmA = ((q & 1) << 3) + rr;
    const int qkA = q >> 1;
    const int qnB = ((q >> 1) << 3) + rr;
    const int qkB = q & 1;

    const unsigned aHiU = (unsigned)__cvta_generic_to_shared(Ahi);
    const unsigned aLoU = (unsigned)__cvta_generic_to_shared(Alo);
    const unsigned bHiU = (unsigned)__cvta_generic_to_shared(Bhi);
    const unsigned bLoU = (unsigned)__cvta_generic_to_shared(Blo);

    const int rwarp = warp_m * WTM;
    const int cwarp = warp_n * WTN;

    unsigned arow[MF];
#pragma unroll
    for (int i = 0; i < MF; i++) arow[i] = (unsigned)(rwarp + i * 16 + qmA) * 128u;
    unsigned brow[NF / 2];
#pragma unroll
    for (int jp = 0; jp < NF / 2; jp++) brow[jp] = (unsigned)(cwarp + jp * 16 + qnB) * 128u;

    float c[MF][NF][4];
#pragma unroll
    for (int i = 0; i < MF; i++)
#pragma unroll
        for (int j = 0; j < NF; j++)
#pragma unroll
            for (int qq = 0; qq < 4; qq++) c[i][j][qq] = 0.0f;

    const uint4 z4 = make_uint4(0u, 0u, 0u, 0u);

#pragma unroll
    for (int kc = 0; kc < 2; kc++) {
        __syncthreads();
        for (int i = t; i < 128 * 8; i += 256) {
            int row = i >> 3, cc = i & 7;
            int grow = r0 + row;
            int dst = row * 64 + ((cc ^ (row & 7)) << 3);
            if (grow < n) {
                *(uint4*)(Ahi + dst) = *(const uint4*)(Xhi + (size_t)grow * 128 + kc * 64 + cc * 8);
                *(uint4*)(Alo + dst) = *(const uint4*)(Xlo + (size_t)grow * 128 + kc * 64 + cc * 8);
            } else {
                *(uint4*)(Ahi + dst) = z4;
                *(uint4*)(Alo + dst) = z4;
            }
        }
        __syncthreads();

        const unsigned bHiP = bHiU + (unsigned)(kc * BPLANE) * 2u;
        const unsigned bLoP = bLoU + (unsigned)(kc * BPLANE) * 2u;

#pragma unroll
        for (int ks = 0; ks < 4; ks++) {
            const int ck = ks * 2;
            unsigned ah[MF][4], al[MF][4], bh[NF][2], bl[NF][2];
#pragma unroll
            for (int i = 0; i < MF; i++) {
                unsigned off = arow[i] + (unsigned)(((ck + qkA) ^ rr) << 4);
                ldsm4(ah[i], aHiU + off);
                ldsm4(al[i], aLoU + off);
            }
#pragma unroll
            for (int jp = 0; jp < NF / 2; jp++) {
                unsigned off = brow[jp] + (unsigned)(((ck + qkB) ^ rr) << 4);
                unsigned tmp[4];
                ldsm4(tmp, bHiP + off);
                bh[2*jp][0] = tmp[0]; bh[2*jp][1] = tmp[1];
                bh[2*jp+1][0] = tmp[2]; bh[2*jp+1][1] = tmp[3];
                ldsm4(tmp, bLoP + off);
                bl[2*jp][0] = tmp[0]; bl[2*jp][1] = tmp[1];
                bl[2*jp+1][0] = tmp[2]; bl[2*jp+1][1] = tmp[3];
            }
#pragma unroll
            for (int i = 0; i < MF; i++)
#pragma unroll
                for (int j = 0; j < NF; j++) {
                    mma16816(c[i][j], ah[i], bh[j]);   // hi*hi
                    mma16816(c[i][j], ah[i], bl[j]);   // hi*lo
                    mma16816(c[i][j], al[i], bh[j]);   // lo*hi
                }
        }
    }

#pragma unroll
    for (int i = 0; i < MF; i++) {
        int row0 = r0 + rwarp + i * 16 + g;
        int row1 = row0 + 8;
#pragma unroll
        for (int j = 0; j < NF; j++) {
            int col = cwarp + j * 8 + 2 * tg;
            if (row0 < n)
                *(float2*)(Y + (size_t)row0 * NC + col) = make_float2(c[i][j][0], c[i][j][1]);
            if (row1 < n)
                *(float2*)(Y + (size_t)row1 * NC + col) = make_float2(c[i][j][2], c[i][j][3]);
        }
    }
}

// ---------------- layer-1 gather (index/dinv software-pipelined) ----------------
__global__ __launch_bounds__(256)
void k_gather_relu(const float* __restrict__ b, int n) {
    int node = (blockIdx.x * blockDim.x + threadIdx.x) >> 5;
    int lane = threadIdx.x & 31;
    if (node >= n) return;

    int e0 = g_off[node], e1 = g_off[node + 1];
    const float4* Y = (const float4*)g_y1;
    float sn = g_dinv[node];

    float4 sv = Y[(size_t)node * 32 + lane];
    float4 a0 = make_float4(sv.x * sn, sv.y * sn, sv.z * sn, sv.w * sn);
    float4 a1 = make_float4(0.f, 0.f, 0.f, 0.f);
    float4 a2 = make_float4(0.f, 0.f, 0.f, 0.f);
    float4 a3 = make_float4(0.f, 0.f, 0.f, 0.f);

    int e = e0;
    int s0 = 0, s1 = 0, s2 = 0, s3 = 0;
    float d0 = 0.f, d1 = 0.f, d2 = 0.f, d3 = 0.f;
    bool have = (e + 3 < e1);
    if (have) {
        s0 = g_csr[e]; s1 = g_csr[e+1]; s2 = g_csr[e+2]; s3 = g_csr[e+3];
        d0 = g_dinv[s0]; d1 = g_dinv[s1]; d2 = g_dinv[s2]; d3 = g_dinv[s3];
    }
    while (have) {
        // current group value loads (independent, issue first)
        float4 v0 = Y[(size_t)s0 * 32 + lane];
        float4 v1 = Y[(size_t)s1 * 32 + lane];
        float4 v2 = Y[(size_t)s2 * 32 + lane];
        float4 v3 = Y[(size_t)s3 * 32 + lane];
        float c0 = d0, c1 = d1, c2 = d2, c3 = d3;
        // prefetch next group's indices + dinv while values are in flight
        e += 4;
        have = (e + 3 < e1);
        if (have) {
            s0 = g_csr[e]; s1 = g_csr[e+1]; s2 = g_csr[e+2]; s3 = g_csr[e+3];
            d0 = g_dinv[s0]; d1 = g_dinv[s1]; d2 = g_dinv[s2]; d3 = g_dinv[s3];
        }
        a0.x = fmaf(v0.x, c0, a0.x); a0.y = fmaf(v0.y, c0, a0.y); a0.z = fmaf(v0.z, c0, a0.z); a0.w = fmaf(v0.w, c0, a0.w);
        a1.x = fmaf(v1.x, c1, a1.x); a1.y = fmaf(v1.y, c1, a1.y); a1.z = fmaf(v1.z, c1, a1.z); a1.w = fmaf(v1.w, c1, a1.w);
        a2.x = fmaf(v2.x, c2, a2.x); a2.y = fmaf(v2.y, c2, a2.y); a2.z = fmaf(v2.z, c2, a2.z); a2.w = fmaf(v2.w, c2, a2.w);
        a3.x = fmaf(v3.x, c3, a3.x); a3.y = fmaf(v3.y, c3, a3.y); a3.z = fmaf(v3.z, c3, a3.z); a3.w = fmaf(v3.w, c3, a3.w);
    }
    for (; e < e1; e++) {
        int ss = g_csr[e];
        float dd = g_dinv[ss];
        float4 v0 = Y[(size_t)ss * 32 + lane];
        a0.x = fmaf(v0.x, dd, a0.x); a0.y = fmaf(v0.y, dd, a0.y); a0.z = fmaf(v0.z, dd, a0.z); a0.w = fmaf(v0.w, dd, a0.w);
    }

    float4 bb = ((const float4*)b)[lane];
    float o0 = fmaxf(fmaf(sn, (a0.x + a1.x) + (a2.x + a3.x), bb.x), 0.0f);
    float o1 = fmaxf(fmaf(sn, (a0.y + a1.y) + (a2.y + a3.y), bb.y), 0.0f);
    float o2 = fmaxf(fmaf(sn, (a0.z + a1.z) + (a2.z + a3.z), bb.z), 0.0f);
    float o3 = fmaxf(fmaf(sn, (a0.w + a1.w) + (a2.w + a3.w), bb.w), 0.0f);

    __nv_bfloat16 h0, h1, h2, h3, l0, l1, l2, l3;
    split1(o0, h0, l0); split1(o1, h1, l1); split1(o2, h2, l2); split1(o3, h3, l3);
    uint2 uh, ul;
    uh.x = ((unsigned)__bfloat16_as_ushort(h1) << 16) | __bfloat16_as_ushort(h0);
    uh.y = ((unsigned)__bfloat16_as_ushort(h3) << 16) | __bfloat16_as_ushort(h2);
    ul.x = ((unsigned)__bfloat16_as_ushort(l1) << 16) | __bfloat16_as_ushort(l0);
    ul.y = ((unsigned)__bfloat16_as_ushort(l3) << 16) | __bfloat16_as_ushort(l2);
    ((uint2*)g_hhi)[(size_t)node * 32 + lane] = uh;
    ((uint2*)g_hlo)[(size_t)node * 32 + lane] = ul;
}

// ---------------- layer-2 gather (pipelined) + bias + log_softmax ----------------
__global__ __launch_bounds__(256)
void k_gather_lsm(const float* __restrict__ b, float* __restrict__ out, int n) {
    int node = (blockIdx.x * blockDim.x + threadIdx.x) >> 5;
    int lane = threadIdx.x & 31;
    if (node >= n) return;

    int e0 = g_off[node], e1 = g_off[node + 1];
    const float2* Y = (const float2*)g_y2;
    float sn = g_dinv[node];

    float2 sv = Y[(size_t)node * 32 + lane];
    float2 a0 = make_float2(sv.x * sn, sv.y * sn);
    float2 a1 = make_float2(0.f, 0.f);
    float2 a2 = make_float2(0.f, 0.f);
    float2 a3 = make_float2(0.f, 0.f);

    int e = e0;
    int s0 = 0, s1 = 0, s2 = 0, s3 = 0;
    float d0 = 0.f, d1 = 0.f, d2 = 0.f, d3 = 0.f;
    bool have = (e + 3 < e1);
    if (have) {
        s0 = g_csr[e]; s1 = g_csr[e+1]; s2 = g_csr[e+2]; s3 = g_csr[e+3];
        d0 = g_dinv[s0]; d1 = g_dinv[s1]; d2 = g_dinv[s2]; d3 = g_dinv[s3];
    }
    while (have) {
        float2 v0 = Y[(size_t)s0 * 32 + lane];
        float2 v1 = Y[(size_t)s1 * 32 + lane];
        float2 v2 = Y[(size_t)s2 * 32 + lane];
        float2 v3 = Y[(size_t)s3 * 32 + lane];
        float c0 = d0, c1 = d1, c2 = d2, c3 = d3;
        e += 4;
        have = (e + 3 < e1);
        if (have) {
            s0 = g_csr[e]; s1 = g_csr[e+1]; s2 = g_csr[e+2]; s3 = g_csr[e+3];
            d0 = g_dinv[s0]; d1 = g_dinv[s1]; d2 = g_dinv[s2]; d3 = g_dinv[s3];
        }
        a0.x = fmaf(v0.x, c0, a0.x); a0.y = fmaf(v0.y, c0, a0.y);
        a1.x = fmaf(v1.x, c1, a1.x); a1.y = fmaf(v1.y, c1, a1.y);
        a2.x = fmaf(v2.x, c2, a2.x); a2.y = fmaf(v2.y, c2, a2.y);
        a3.x = fmaf(v3.x, c3, a3.x); a3.y = fmaf(v3.y, c3, a3.y);
    }
    for (; e < e1; e++) {
        int ss = g_csr[e];
        float dd = g_dinv[ss];
        float2 v0 = Y[(size_t)ss * 32 + lane];
        a0.x = fmaf(v0.x, dd, a0.x); a0.y = fmaf(v0.y, dd, a0.y);
    }

    float2 bb = ((const float2*)b)[lane];
    float t0 = fmaf(sn, (a0.x + a1.x) + (a2.x + a3.x), bb.x);
    float t1 = fmaf(sn, (a0.y + a1.y) + (a2.y + a3.y), bb.y);

    float m = fmaxf(t0, t1);
#pragma unroll
    for (int o = 16; o; o >>= 1) m = fmaxf(m, __shfl_xor_sync(0xffffffffu, m, o));
    float ex = expf(t0 - m) + expf(t1 - m);
#pragma unroll
    for (int o = 16; o; o >>= 1) ex += __shfl_xor_sync(0xffffffffu, ex, o);
    float ls = m + logf(ex);

    ((float2*)out)[(size_t)node * 32 + lane] = make_float2(t0 - ls, t1 - ls);
}

// ---------------- host launch ----------------
extern "C" void kernel_launch(void* const* d_in, const int* in_sizes, int n_in,
                              void* d_out, int out_size) {
    const float* x   = (const float*)d_in[0];
    const void*  ei  = d_in[1];
    const float* W1  = (const float*)d_in[2];
    const float* b1  = (const float*)d_in[3];
    const float* W2  = (const float*)d_in[4];
    const float* b2  = (const float*)d_in[5];
    float*       out = (float*)d_out;

    const int N = in_sizes[0] / FDIM;      // 100000
    const int E = in_sizes[1] / 2;         // 1600000

    const int SMEM1 = (2 * 128 * 64 + 4 * 128 * 64) * (int)sizeof(__nv_bfloat16);  // 98304
    const int SMEM2 = (2 * 128 * 64 + 4 * 64  * 64) * (int)sizeof(__nv_bfloat16);  // 65536
    cudaFuncSetAttribute(k_gemm_mma<128, 0>, cudaFuncAttributeMaxDynamicSharedMemorySize, SMEM1);
    cudaFuncSetAttribute(k_gemm_mma<64, 1>,  cudaFuncAttributeMaxDynamicSharedMemorySize, SMEM2);

    static cudaStream_t s2 = nullptr;
    static cudaEvent_t  evFork = nullptr, evJoin = nullptr;
    if (!s2) {
        cudaStreamCreateWithFlags(&s2, cudaStreamNonBlocking);
        cudaEventCreateWithFlags(&evFork, cudaEventDisableTiming);
        cudaEventCreateWithFlags(&evJoin, cudaEventDisableTiming);
    }

    const int nb = (N + SCAN_CH - 1) / SCAN_CH;

    // main stream: prep, then GEMM chain
    k_prep        <<<(N + 255) / 256, 256>>>((const unsigned int*)ei, N);        // 0
    cudaEventRecord(evFork, 0);
    k_split_x     <<<(N * 32 + 255) / 256, 256>>>(x, N * 32);                    // 1
    k_split_w_both<<<(128 * 192 + 255) / 256, 256>>>(W1, W2);                    // 2
    k_gemm_mma<128, 0><<<(N + 127) / 128, 256, SMEM1>>>(N);                      // 3 <- profiled

    // side stream: CSR build chain
    cudaStreamWaitEvent(s2, evFork, 0);
    k_count   <<<(E + 255) / 256, 256, 0, s2>>>(ei, E);
    k_scan1   <<<nb, SCAN_CH, 0, s2>>>(N);
    k_scan2   <<<1, 256, 0, s2>>>(nb);
    k_scan3   <<<(N + 255) / 256, 256, 0, s2>>>(N, E);
    k_fill_csr<<<(E + 255) / 256, 256, 0, s2>>>(ei, E);
    cudaEventRecord(evJoin, s2);

    // join, then aggregation + layer 2
    cudaStreamWaitEvent(0, evJoin, 0);
    k_gather_relu<<<(N * 32 + 255) / 256, 256>>>(b1, N);
    k_gemm_mma<64, 1><<<(N + 127) / 128, 256, SMEM2>>>(N);
    k_gather_lsm<<<(N * 32 + 255) / 256, 256>>>(b2, out, N);
}

// round 17
// speedup vs baseline: 1.4016x; 1.0924x over previous
#include <cuda_runtime.h>
#include <cuda_bf16.h>
#include <math.h>

#define NMAX 100000
#define EMAX 1600000
#define FDIM 128
#define CDIM 64
#define SCAN_CH 512
#define NBLK ((NMAX + SCAN_CH - 1) / SCAN_CH)   // 196

// ---------------- device scratch (referenced ONLY in device code) ----------------
__device__ float g_dinv[NMAX];
__device__ float g_y1 [NMAX * FDIM];   // y1 = x@W1 (unscaled, f32 messages)
__device__ float g_y2 [NMAX * CDIM];   // y2 = h@W2 (unscaled, f32 messages)
__device__ __nv_bfloat16 g_xhi[NMAX * FDIM], g_xlo[NMAX * FDIM];   // split of x
__device__ __nv_bfloat16 g_hhi[NMAX * FDIM], g_hlo[NMAX * FDIM];   // split of h (relu out)
__device__ __nv_bfloat16 g_w1hi[FDIM * FDIM], g_w1lo[FDIM * FDIM]; // W1^T [n][k]
__device__ __nv_bfloat16 g_w2hi[CDIM * FDIM], g_w2lo[CDIM * FDIM]; // W2^T [n][k]
__device__ int   g_csr[EMAX];
__device__ int   g_cnt[NMAX];
__device__ int   g_off[NMAX + 1];
__device__ int   g_cur[NMAX];
__device__ int   g_bsum[NBLK];
__device__ int   g_is64;

// ---------------- prep: dtype detect (block 0) + zero cnt ----------------
__global__ void k_prep(const unsigned int* __restrict__ w, int n) {
    int i = blockIdx.x * blockDim.x + threadIdx.x;
    if (i < n) g_cnt[i] = 0;
    if (blockIdx.x == 0) {
        __shared__ unsigned int s;
        if (threadIdx.x == 0) s = 0u;
        __syncthreads();
        if (threadIdx.x < 128) atomicOr(&s, w[2 * threadIdx.x + 1]);  // int64 -> odd words 0
        __syncthreads();
        if (threadIdx.x == 0) g_is64 = (s == 0u) ? 1 : 0;
    }
}

// ---------------- f32 -> bf16 hi/lo split helpers ----------------
__device__ __forceinline__ void split1(float f, __nv_bfloat16& hi, __nv_bfloat16& lo) {
    hi = __float2bfloat16_rn(f);
    lo = __float2bfloat16_rn(f - __bfloat162float(hi));
}

__global__ void k_split_x(const float* __restrict__ X, int n4) {
    int i = blockIdx.x * blockDim.x + threadIdx.x;
    if (i >= n4) return;
    float4 v = ((const float4*)X)[i];
    __nv_bfloat16 h0, h1, h2, h3, l0, l1, l2, l3;
    split1(v.x, h0, l0); split1(v.y, h1, l1); split1(v.z, h2, l2); split1(v.w, h3, l3);
    uint2 uh, ul;
    uh.x = ((unsigned)__bfloat16_as_ushort(h1) << 16) | __bfloat16_as_ushort(h0);
    uh.y = ((unsigned)__bfloat16_as_ushort(h3) << 16) | __bfloat16_as_ushort(h2);
    ul.x = ((unsigned)__bfloat16_as_ushort(l1) << 16) | __bfloat16_as_ushort(l0);
    ul.y = ((unsigned)__bfloat16_as_ushort(l3) << 16) | __bfloat16_as_ushort(l2);
    ((uint2*)g_xhi)[i] = uh;
    ((uint2*)g_xlo)[i] = ul;
}

__global__ void k_split_w_both(const float* __restrict__ W1, const float* __restrict__ W2) {
    int i = blockIdx.x * blockDim.x + threadIdx.x;
    if (i < 128 * 128) {
        int k = i / 128, nn = i % 128;
        __nv_bfloat16 hi, lo;
        split1(W1[i], hi, lo);
        g_w1hi[nn * 128 + k] = hi;
        g_w1lo[nn * 128 + k] = lo;
    } else if (i < 128 * 128 + 128 * 64) {
        int j = i - 128 * 128;
        int k = j / 64, nn = j % 64;
        __nv_bfloat16 hi, lo;
        split1(W2[j], hi, lo);
        g_w2hi[nn * 128 + k] = hi;
        g_w2lo[nn * 128 + k] = lo;
    }
}

// ---------------- degree count ----------------
__global__ void k_count(const void* __restrict__ ei, int E) {
    int e = blockIdx.x * blockDim.x + threadIdx.x;
    if (e >= E) return;
    int d = g_is64 ? (int)((const long long*)ei)[E + e] : ((const int*)ei)[E + e];
    atomicAdd(&g_cnt[d], 1);
}

// ---------------- exclusive scan of g_cnt -> g_off (+ fused dinv) ----------------
__global__ void k_scan1(int n) {
    __shared__ int sm[SCAN_CH];
    int t = threadIdx.x, b = blockIdx.x;
    int i = b * SCAN_CH + t;
    int v = (i < n) ? g_cnt[i] : 0;
    if (i < n) g_dinv[i] = rsqrtf((float)(v + 1));
    sm[t] = v;
    __syncthreads();
#pragma unroll
    for (int off = 1; off < SCAN_CH; off <<= 1) {
        int tv = (t >= off) ? sm[t - off] : 0;
        __syncthreads();
        sm[t] += tv;
        __syncthreads();
    }
    if (i < n) g_off[i] = sm[t] - v;
    if (t == SCAN_CH - 1) g_bsum[b] = sm[t];
}

__global__ void k_scan2(int nb) {
    __shared__ int sm[256];
    int t = threadIdx.x;
    int v = (t < nb) ? g_bsum[t] : 0;
    sm[t] = v;
    __syncthreads();
#pragma unroll
    for (int off = 1; off < 256; off <<= 1) {
        int tv = (t >= off) ? sm[t - off] : 0;
        __syncthreads();
        sm[t] += tv;
        __syncthreads();
    }
    if (t < nb) g_bsum[t] = sm[t] - v;
}

__global__ void k_scan3(int n, int E) {
    int i = blockIdx.x * blockDim.x + threadIdx.x;
    if (i < n) {
        int o = g_off[i] + g_bsum[i / SCAN_CH];
        g_off[i] = o;
        g_cur[i] = o;
    }
    if (i == 0) g_off[n] = E;
}

__global__ void k_fill_csr(const void* __restrict__ ei, int E) {
    int e = blockIdx.x * blockDim.x + threadIdx.x;
    if (e >= E) return;
    int s, d;
    if (g_is64) {
        const long long* p = (const long long*)ei;
        s = (int)p[e];  d = (int)p[E + e];
    } else {
        const int* p = (const int*)ei;
        s = p[e];  d = p[E + e];
    }
    int pos = atomicAdd(&g_cur[d], 1);
    g_csr[pos] = s;
}

// ---------------- bf16 split-precision tensor-core GEMM (ldmatrix + swizzle) ----------------
__device__ __forceinline__ void mma16816(float* c, const unsigned* a, const unsigned* b) {
    asm volatile(
        "mma.sync.aligned.m16n8k16.row.col.f32.bf16.bf16.f32 "
        "{%0,%1,%2,%3}, {%4,%5,%6,%7}, {%8,%9}, {%0,%1,%2,%3};"
        : "+f"(c[0]), "+f"(c[1]), "+f"(c[2]), "+f"(c[3])
        : "r"(a[0]), "r"(a[1]), "r"(a[2]), "r"(a[3]), "r"(b[0]), "r"(b[1]));
}

__device__ __forceinline__ void ldsm4(unsigned* d, unsigned addr) {
    asm volatile("ldmatrix.sync.aligned.m8n8.x4.shared.b16 {%0,%1,%2,%3}, [%4];"
                 : "=r"(d[0]), "=r"(d[1]), "=r"(d[2]), "=r"(d[3]) : "r"(addr));
}

template <int NC, int LAYER>
__global__ __launch_bounds__(256, 2)
void k_gemm_mma(int n) {
    const __nv_bfloat16* Xhi = (LAYER == 0) ? g_xhi : g_hhi;
    const __nv_bfloat16* Xlo = (LAYER == 0) ? g_xlo : g_hlo;
    const __nv_bfloat16* Whi = (LAYER == 0) ? g_w1hi : g_w2hi;
    const __nv_bfloat16* Wlo = (LAYER == 0) ? g_w1lo : g_w2lo;
    float*               Y   = (LAYER == 0) ? g_y1 : g_y2;

    constexpr int WM = (NC == 128) ? 2 : 4;
    constexpr int WN = 8 / WM;
    constexpr int WTM = 128 / WM;
    constexpr int WTN = NC / WN;
    constexpr int MF = WTM / 16;      // 4 / 2
    constexpr int NF = WTN / 8;       // 4
    constexpr int APLANE = 128 * 64;
    constexpr int BPLANE = NC * 64;

    extern __shared__ __nv_bfloat16 smb[];
    __nv_bfloat16* Ahi = smb;
    __nv_bfloat16* Alo = Ahi + APLANE;
    __nv_bfloat16* Bhi = Alo + APLANE;
    __nv_bfloat16* Blo = Bhi + 2 * BPLANE;

    const int t  = threadIdx.x;
    const int r0 = blockIdx.x * 128;

    for (int i = t; i < NC * 16; i += 256) {
        int row = i >> 4, c = i & 15;
        int p = c >> 3, cc = c & 7;
        int dst = p * BPLANE + row * 64 + ((cc ^ (row & 7)) << 3);
        *(uint4*)(Bhi + dst) = *(const uint4*)(Whi + row * 128 + p * 64 + cc * 8);
        *(uint4*)(Blo + dst) = *(const uint4*)(Wlo + row * 128 + p * 64 + cc * 8);
    }

    const int wid    = t >> 5;
    const int lane   = t & 31;
    const int warp_m = wid / WN;
    const int warp_n = wid % WN;
    const int g  = lane >> 2;
    const int tg = lane & 3;
    const int q  = lane >> 3;
    const int rr = lane & 7;

    const int qmA = ((q & 1) << 3) + rr;
    const int qkA = q >> 1;
    const int qnB = ((q >> 1) << 3) + rr;
    const int qkB = q & 1;

    const unsigned aHiU = (unsigned)__cvta_generic_to_shared(Ahi);
    const unsigned aLoU = (unsigned)__cvta_generic_to_shared(Alo);
    const unsigned bHiU = (unsigned)__cvta_generic_to_shared(Bhi);
    const unsigned bLoU = (unsigned)__cvta_generic_to_shared(Blo);

    const int rwarp = warp_m * WTM;
    const int cwarp = warp_n * WTN;

    unsigned arow[MF];
#pragma unroll
    for (int i = 0; i < MF; i++) arow[i] = (unsigned)(rwarp + i * 16 + qmA) * 128u;
    unsigned brow[NF / 2];
#pragma unroll
    for (int jp = 0; jp < NF / 2; jp++) brow[jp] = (unsigned)(cwarp + jp * 16 + qnB) * 128u;

    float c[MF][NF][4];
#pragma unroll
    for (int i = 0; i < MF; i++)
#pragma unroll
        for (int j = 0; j < NF; j++)
#pragma unroll
            for (int qq = 0; qq < 4; qq++) c[i][j][qq] = 0.0f;

    const uint4 z4 = make_uint4(0u, 0u, 0u, 0u);

#pragma unroll
    for (int kc = 0; kc < 2; kc++) {
        __syncthreads();
        for (int i = t; i < 128 * 8; i += 256) {
            int row = i >> 3, cc = i & 7;
            int grow = r0 + row;
            int dst = row * 64 + ((cc ^ (row & 7)) << 3);
            if (grow < n) {
                *(uint4*)(Ahi + dst) = *(const uint4*)(Xhi + (size_t)grow * 128 + kc * 64 + cc * 8);
                *(uint4*)(Alo + dst) = *(const uint4*)(Xlo + (size_t)grow * 128 + kc * 64 + cc * 8);
            } else {
                *(uint4*)(Ahi + dst) = z4;
                *(uint4*)(Alo + dst) = z4;
            }
        }
        __syncthreads();

        const unsigned bHiP = bHiU + (unsigned)(kc * BPLANE) * 2u;
        const unsigned bLoP = bLoU + (unsigned)(kc * BPLANE) * 2u;

#pragma unroll
        for (int ks = 0; ks < 4; ks++) {
            const int ck = ks * 2;
            unsigned ah[MF][4], al[MF][4], bh[NF][2], bl[NF][2];
#pragma unroll
            for (int i = 0; i < MF; i++) {
                unsigned off = arow[i] + (unsigned)(((ck + qkA) ^ rr) << 4);
                ldsm4(ah[i], aHiU + off);
                ldsm4(al[i], aLoU + off);
            }
#pragma unroll
            for (int jp = 0; jp < NF / 2; jp++) {
                unsigned off = brow[jp] + (unsigned)(((ck + qkB) ^ rr) << 4);
                unsigned tmp[4];
                ldsm4(tmp, bHiP + off);
                bh[2*jp][0] = tmp[0]; bh[2*jp][1] = tmp[1];
                bh[2*jp+1][0] = tmp[2]; bh[2*jp+1][1] = tmp[3];
                ldsm4(tmp, bLoP + off);
                bl[2*jp][0] = tmp[0]; bl[2*jp][1] = tmp[1];
                bl[2*jp+1][0] = tmp[2]; bl[2*jp+1][1] = tmp[3];
            }
#pragma unroll
            for (int i = 0; i < MF; i++)
#pragma unroll
                for (int j = 0; j < NF; j++) {
                    mma16816(c[i][j], ah[i], bh[j]);   // hi*hi
                    mma16816(c[i][j], ah[i], bl[j]);   // hi*lo
                    mma16816(c[i][j], al[i], bh[j]);   // lo*hi
                }
        }
    }

#pragma unroll
    for (int i = 0; i < MF; i++) {
        int row0 = r0 + rwarp + i * 16 + g;
        int row1 = row0 + 8;
#pragma unroll
        for (int j = 0; j < NF; j++) {
            int col = cwarp + j * 8 + 2 * tg;
            if (row0 < n)
                *(float2*)(Y + (size_t)row0 * NC + col) = make_float2(c[i][j][0], c[i][j][1]);
            if (row1 < n)
                *(float2*)(Y + (size_t)row1 * NC + col) = make_float2(c[i][j][2], c[i][j][3]);
        }
    }
}

// ---------------- layer-1 gather: plain loop, 8-way unroll (compiler batches loads) ----------------
__global__ __launch_bounds__(256)
void k_gather_relu(const float* __restrict__ b, int n) {
    int node = (blockIdx.x * blockDim.x + threadIdx.x) >> 5;
    int lane = threadIdx.x & 31;
    if (node >= n) return;

    int e0 = g_off[node], e1 = g_off[node + 1];
    const float4* Y = (const float4*)g_y1;
    float sn = g_dinv[node];

    float4 sv = Y[(size_t)node * 32 + lane];
    float4 a0 = make_float4(sv.x * sn, sv.y * sn, sv.z * sn, sv.w * sn);
    float4 a1 = make_float4(0.f, 0.f, 0.f, 0.f);
    float4 a2 = make_float4(0.f, 0.f, 0.f, 0.f);
    float4 a3 = make_float4(0.f, 0.f, 0.f, 0.f);

    int e = e0;
    for (; e + 7 < e1; e += 8) {
        int s0 = g_csr[e],   s1 = g_csr[e+1], s2 = g_csr[e+2], s3 = g_csr[e+3];
        int s4 = g_csr[e+4], s5 = g_csr[e+5], s6 = g_csr[e+6], s7 = g_csr[e+7];
        float d0 = g_dinv[s0], d1 = g_dinv[s1], d2 = g_dinv[s2], d3 = g_dinv[s3];
        float d4 = g_dinv[s4], d5 = g_dinv[s5], d6 = g_dinv[s6], d7 = g_dinv[s7];
        float4 v0 = Y[(size_t)s0 * 32 + lane];
        float4 v1 = Y[(size_t)s1 * 32 + lane];
        float4 v2 = Y[(size_t)s2 * 32 + lane];
        float4 v3 = Y[(size_t)s3 * 32 + lane];
        float4 v4 = Y[(size_t)s4 * 32 + lane];
        float4 v5 = Y[(size_t)s5 * 32 + lane];
        float4 v6 = Y[(size_t)s6 * 32 + lane];
        float4 v7 = Y[(size_t)s7 * 32 + lane];
        a0.x = fmaf(v0.x, d0, a0.x); a0.y = fmaf(v0.y, d0, a0.y); a0.z = fmaf(v0.z, d0, a0.z); a0.w = fmaf(v0.w, d0, a0.w);
        a1.x = fmaf(v1.x, d1, a1.x); a1.y = fmaf(v1.y, d1, a1.y); a1.z = fmaf(v1.z, d1, a1.z); a1.w = fmaf(v1.w, d1, a1.w);
        a2.x = fmaf(v2.x, d2, a2.x); a2.y = fmaf(v2.y, d2, a2.y); a2.z = fmaf(v2.z, d2, a2.z); a2.w = fmaf(v2.w, d2, a2.w);
        a3.x = fmaf(v3.x, d3, a3.x); a3.y = fmaf(v3.y, d3, a3.y); a3.z = fmaf(v3.z, d3, a3.z); a3.w = fmaf(v3.w, d3, a3.w);
        a0.x = fmaf(v4.x, d4, a0.x); a0.y = fmaf(v4.y, d4, a0.y); a0.z = fmaf(v4.z, d4, a0.z); a0.w = fmaf(v4.w, d4, a0.w);
        a1.x = fmaf(v5.x, d5, a1.x); a1.y = fmaf(v5.y, d5, a1.y); a1.z = fmaf(v5.z, d5, a1.z); a1.w = fmaf(v5.w, d5, a1.w);
        a2.x = fmaf(v6.x, d6, a2.x); a2.y = fmaf(v6.y, d6, a2.y); a2.z = fmaf(v6.z, d6, a2.z); a2.w = fmaf(v6.w, d6, a2.w);
        a3.x = fmaf(v7.x, d7, a3.x); a3.y = fmaf(v7.y, d7, a3.y); a3.z = fmaf(v7.z, d7, a3.z); a3.w = fmaf(v7.w, d7, a3.w);
    }
    for (; e + 3 < e1; e += 4) {
        int s0 = g_csr[e], s1 = g_csr[e+1], s2 = g_csr[e+2], s3 = g_csr[e+3];
        float d0 = g_dinv[s0], d1 = g_dinv[s1], d2 = g_dinv[s2], d3 = g_dinv[s3];
        float4 v0 = Y[(size_t)s0 * 32 + lane];
        float4 v1 = Y[(size_t)s1 * 32 + lane];
        float4 v2 = Y[(size_t)s2 * 32 + lane];
        float4 v3 = Y[(size_t)s3 * 32 + lane];
        a0.x = fmaf(v0.x, d0, a0.x); a0.y = fmaf(v0.y, d0, a0.y); a0.z = fmaf(v0.z, d0, a0.z); a0.w = fmaf(v0.w, d0, a0.w);
        a1.x = fmaf(v1.x, d1, a1.x); a1.y = fmaf(v1.y, d1, a1.y); a1.z = fmaf(v1.z, d1, a1.z); a1.w = fmaf(v1.w, d1, a1.w);
        a2.x = fmaf(v2.x, d2, a2.x); a2.y = fmaf(v2.y, d2, a2.y); a2.z = fmaf(v2.z, d2, a2.z); a2.w = fmaf(v2.w, d2, a2.w);
        a3.x = fmaf(v3.x, d3, a3.x); a3.y = fmaf(v3.y, d3, a3.y); a3.z = fmaf(v3.z, d3, a3.z); a3.w = fmaf(v3.w, d3, a3.w);
    }
    for (; e < e1; e++) {
        int s0 = g_csr[e];
        float d0 = g_dinv[s0];
        float4 v0 = Y[(size_t)s0 * 32 + lane];
        a0.x = fmaf(v0.x, d0, a0.x); a0.y = fmaf(v0.y, d0, a0.y); a0.z = fmaf(v0.z, d0, a0.z); a0.w = fmaf(v0.w, d0, a0.w);
    }

    float4 bb = ((const float4*)b)[lane];
    float o0 = fmaxf(fmaf(sn, (a0.x + a1.x) + (a2.x + a3.x), bb.x), 0.0f);
    float o1 = fmaxf(fmaf(sn, (a0.y + a1.y) + (a2.y + a3.y), bb.y), 0.0f);
    float o2 = fmaxf(fmaf(sn, (a0.z + a1.z) + (a2.z + a3.z), bb.z), 0.0f);
    float o3 = fmaxf(fmaf(sn, (a0.w + a1.w) + (a2.w + a3.w), bb.w), 0.0f);

    __nv_bfloat16 h0, h1, h2, h3, l0, l1, l2, l3;
    split1(o0, h0, l0); split1(o1, h1, l1); split1(o2, h2, l2); split1(o3, h3, l3);
    uint2 uh, ul;
    uh.x = ((unsigned)__bfloat16_as_ushort(h1) << 16) | __bfloat16_as_ushort(h0);
    uh.y = ((unsigned)__bfloat16_as_ushort(h3) << 16) | __bfloat16_as_ushort(h2);
    ul.x = ((unsigned)__bfloat16_as_ushort(l1) << 16) | __bfloat16_as_ushort(l0);
    ul.y = ((unsigned)__bfloat16_as_ushort(l3) << 16) | __bfloat16_as_ushort(l2);
    ((uint2*)g_hhi)[(size_t)node * 32 + lane] = uh;
    ((uint2*)g_hlo)[(size_t)node * 32 + lane] = ul;
}

// ---------------- layer-2 gather (8-way unroll) + bias + log_softmax ----------------
__global__ __launch_bounds__(256)
void k_gather_lsm(const float* __restrict__ b, float* __restrict__ out, int n) {
    int node = (blockIdx.x * blockDim.x + threadIdx.x) >> 5;
    int lane = threadIdx.x & 31;
    if (node >= n) return;

    int e0 = g_off[node], e1 = g_off[node + 1];
    const float2* Y = (const float2*)g_y2;
    float sn = g_dinv[node];

    float2 sv = Y[(size_t)node * 32 + lane];
    float2 a0 = make_float2(sv.x * sn, sv.y * sn);
    float2 a1 = make_float2(0.f, 0.f);
    float2 a2 = make_float2(0.f, 0.f);
    float2 a3 = make_float2(0.f, 0.f);

    int e = e0;
    for (; e + 7 < e1; e += 8) {
        int s0 = g_csr[e],   s1 = g_csr[e+1], s2 = g_csr[e+2], s3 = g_csr[e+3];
        int s4 = g_csr[e+4], s5 = g_csr[e+5], s6 = g_csr[e+6], s7 = g_csr[e+7];
        float d0 = g_dinv[s0], d1 = g_dinv[s1], d2 = g_dinv[s2], d3 = g_dinv[s3];
        float d4 = g_dinv[s4], d5 = g_dinv[s5], d6 = g_dinv[s6], d7 = g_dinv[s7];
        float2 v0 = Y[(size_t)s0 * 32 + lane];
        float2 v1 = Y[(size_t)s1 * 32 + lane];
        float2 v2 = Y[(size_t)s2 * 32 + lane];
        float2 v3 = Y[(size_t)s3 * 32 + lane];
        float2 v4 = Y[(size_t)s4 * 32 + lane];
        float2 v5 = Y[(size_t)s5 * 32 + lane];
        float2 v6 = Y[(size_t)s6 * 32 + lane];
        float2 v7 = Y[(size_t)s7 * 32 + lane];
        a0.x = fmaf(v0.x, d0, a0.x); a0.y = fmaf(v0.y, d0, a0.y);
        a1.x = fmaf(v1.x, d1, a1.x); a1.y = fmaf(v1.y, d1, a1.y);
        a2.x = fmaf(v2.x, d2, a2.x); a2.y = fmaf(v2.y, d2, a2.y);
        a3.x = fmaf(v3.x, d3, a3.x); a3.y = fmaf(v3.y, d3, a3.y);
        a0.x = fmaf(v4.x, d4, a0.x); a0.y = fmaf(v4.y, d4, a0.y);
        a1.x = fmaf(v5.x, d5, a1.x); a1.y = fmaf(v5.y, d5, a1.y);
        a2.x = fmaf(v6.x, d6, a2.x); a2.y = fmaf(v6.y, d6, a2.y);
        a3.x = fmaf(v7.x, d7, a3.x); a3.y = fmaf(v7.y, d7, a3.y);
    }
    for (; e + 3 < e1; e += 4) {
        int s0 = g_csr[e], s1 = g_csr[e+1], s2 = g_csr[e+2], s3 = g_csr[e+3];
        float d0 = g_dinv[s0], d1 = g_dinv[s1], d2 = g_dinv[s2], d3 = g_dinv[s3];
        float2 v0 = Y[(size_t)s0 * 32 + lane];
        float2 v1 = Y[(size_t)s1 * 32 + lane];
        float2 v2 = Y[(size_t)s2 * 32 + lane];
        float2 v3 = Y[(size_t)s3 * 32 + lane];
        a0.x = fmaf(v0.x, d0, a0.x); a0.y = fmaf(v0.y, d0, a0.y);
        a1.x = fmaf(v1.x, d1, a1.x); a1.y = fmaf(v1.y, d1, a1.y);
        a2.x = fmaf(v2.x, d2, a2.x); a2.y = fmaf(v2.y, d2, a2.y);
        a3.x = fmaf(v3.x, d3, a3.x); a3.y = fmaf(v3.y, d3, a3.y);
    }
    for (; e < e1; e++) {
        int s0 = g_csr[e];
        float d0 = g_dinv[s0];
        float2 v0 = Y[(size_t)s0 * 32 + lane];
        a0.x = fmaf(v0.x, d0, a0.x); a0.y = fmaf(v0.y, d0, a0.y);
    }

    float2 bb = ((const float2*)b)[lane];
    float t0 = fmaf(sn, (a0.x + a1.x) + (a2.x + a3.x), bb.x);
    float t1 = fmaf(sn, (a0.y + a1.y) + (a2.y + a3.y), bb.y);

    float m = fmaxf(t0, t1);
#pragma unroll
    for (int o = 16; o; o >>= 1) m = fmaxf(m, __shfl_xor_sync(0xffffffffu, m, o));
    float ex = expf(t0 - m) + expf(t1 - m);
#pragma unroll
    for (int o = 16; o; o >>= 1) ex += __shfl_xor_sync(0xffffffffu, ex, o);
    float ls = m + logf(ex);

    ((float2*)out)[(size_t)node * 32 + lane] = make_float2(t0 - ls, t1 - ls);
}

// ---------------- host launch ----------------
extern "C" void kernel_launch(void* const* d_in, const int* in_sizes, int n_in,
                              void* d_out, int out_size) {
    const float* x   = (const float*)d_in[0];
    const void*  ei  = d_in[1];
    const float* W1  = (const float*)d_in[2];
    const float* b1  = (const float*)d_in[3];
    const float* W2  = (const float*)d_in[4];
    const float* b2  = (const float*)d_in[5];
    float*       out = (float*)d_out;

    const int N = in_sizes[0] / FDIM;      // 100000
    const int E = in_sizes[1] / 2;         // 1600000

    const int SMEM1 = (2 * 128 * 64 + 4 * 128 * 64) * (int)sizeof(__nv_bfloat16);  // 98304
    const int SMEM2 = (2 * 128 * 64 + 4 * 64  * 64) * (int)sizeof(__nv_bfloat16);  // 65536
    cudaFuncSetAttribute(k_gemm_mma<128, 0>, cudaFuncAttributeMaxDynamicSharedMemorySize, SMEM1);
    cudaFuncSetAttribute(k_gemm_mma<64, 1>,  cudaFuncAttributeMaxDynamicSharedMemorySize, SMEM2);

    static cudaStream_t s2 = nullptr;
    static cudaEvent_t  evFork = nullptr, evJoin = nullptr;
    if (!s2) {
        cudaStreamCreateWithFlags(&s2, cudaStreamNonBlocking);
        cudaEventCreateWithFlags(&evFork, cudaEventDisableTiming);
        cudaEventCreateWithFlags(&evJoin, cudaEventDisableTiming);
    }

    const int nb = (N + SCAN_CH - 1) / SCAN_CH;

    // main stream: prep, then GEMM chain
    k_prep        <<<(N + 255) / 256, 256>>>((const unsigned int*)ei, N);        // 0
    cudaEventRecord(evFork, 0);
    k_split_x     <<<(N * 32 + 255) / 256, 256>>>(x, N * 32);                    // 1
    k_split_w_both<<<(128 * 192 + 255) / 256, 256>>>(W1, W2);                    // 2
    k_gemm_mma<128, 0><<<(N + 127) / 128, 256, SMEM1>>>(N);                      // 3 <- profiled

    // side stream: CSR build chain
    cudaStreamWaitEvent(s2, evFork, 0);
    k_count   <<<(E + 255) / 256, 256, 0, s2>>>(ei, E);
    k_scan1   <<<nb, SCAN_CH, 0, s2>>>(N);
    k_scan2   <<<1, 256, 0, s2>>>(nb);
    k_scan3   <<<(N + 255) / 256, 256, 0, s2>>>(N, E);
    k_fill_csr<<<(E + 255) / 256, 256, 0, s2>>>(ei, E);
    cudaEventRecord(evJoin, s2);

    // join, then aggregation + layer 2
    cudaStreamWaitEvent(0, evJoin, 0);
    k_gather_relu<<<(N * 32 + 255) / 256, 256>>>(b1, N);
    k_gemm_mma<64, 1><<<(N + 127) / 128, 256, SMEM2>>>(N);
    k_gather_lsm<<<(N * 32 + 255) / 256, 256>>>(b2, out, N);
}